// round 11
// baseline (speedup 1.0000x reference)
#include <cuda_runtime.h>
#include <cuda_bf16.h>
#include <math.h>
#include <stdint.h>

#define NMAX 50000
#define NPAD 50048   // 391 * 128
#define EMAX 400000

// ------------------------- scratch (static device memory) -------------------------
__device__ float g_q[(size_t)NPAD * 256];
__device__ float g_k[(size_t)NPAD * 256];
__device__ float g_v[(size_t)NPAD * 256];
__device__ float g_p[(size_t)NPAD * 256];
__device__ float g_skip1[(size_t)NPAD * 256];
__device__ float g_attn[(size_t)NPAD * 256];
__device__ float g_accea[(size_t)NPAD * 256];
__device__ float g_h[(size_t)NPAD * 256];
__device__ float g_skip2[(size_t)NPAD * 32];
__device__ __nv_bfloat16 g_ah[(size_t)NPAD * 256];
__device__ __nv_bfloat16 g_al[(size_t)NPAD * 256];
__device__ __nv_bfloat16 g_bth[1024 * 256];
__device__ __nv_bfloat16 g_btl[1024 * 256];
__device__ int g_deg[NMAX];
__device__ int g_rowptr[NMAX + 1];
__device__ int g_cnt[NMAX];
__device__ int g_eid[EMAX];
__device__ int g_esrc[EMAX];

// ------------------------- PTX helpers -------------------------
__device__ __forceinline__ uint32_t smem_u32(const void* p) {
    uint32_t a;
    asm("{ .reg .u64 t; cvta.to.shared.u64 t, %1; cvt.u32.u64 %0, t; }" : "=r"(a) : "l"(p));
    return a;
}
__device__ __forceinline__ void cp16(uint32_t saddr, const void* gaddr) {
    asm volatile("cp.async.cg.shared.global [%0], [%1], 16;" :: "r"(saddr), "l"(gaddr) : "memory");
}
#define CP_COMMIT() asm volatile("cp.async.commit_group;" ::: "memory")
#define CP_WAIT(N)  asm volatile("cp.async.wait_group %0;" :: "n"(N) : "memory")

__device__ __forceinline__ void ldm_x4(uint32_t* r, uint32_t addr) {
    asm volatile("ldmatrix.sync.aligned.m8n8.x4.shared.b16 {%0,%1,%2,%3}, [%4];"
        : "=r"(r[0]), "=r"(r[1]), "=r"(r[2]), "=r"(r[3]) : "r"(addr));
}
__device__ __forceinline__ void mma_bf16(float* c, const uint32_t* a, const uint32_t* b) {
    asm volatile("mma.sync.aligned.m16n8k16.row.col.f32.bf16.bf16.f32 "
        "{%0,%1,%2,%3}, {%4,%5,%6,%7}, {%8,%9}, {%0,%1,%2,%3};"
        : "+f"(c[0]), "+f"(c[1]), "+f"(c[2]), "+f"(c[3])
        : "r"(a[0]), "r"(a[1]), "r"(a[2]), "r"(a[3]), "r"(b[0]), "r"(b[1]));
}

// ------------------------- CSR build -------------------------
__global__ void zero_deg_kernel(int n) {
    int i = blockIdx.x * blockDim.x + threadIdx.x;
    if (i < n) g_deg[i] = 0;
}
__global__ void hist_kernel(const int* __restrict__ dst, int e) {
    int i = blockIdx.x * blockDim.x + threadIdx.x;
    if (i < e) atomicAdd(&g_deg[dst[i]], 1);
}
__global__ void scan_kernel(int n) {
    __shared__ int sums[1024];
    int tid = threadIdx.x;
    int per = (n + 1023) >> 10;
    int beg = tid * per;
    int end = min(beg + per, n);
    int s = 0;
    for (int i = beg; i < end; i++) s += g_deg[i];
    sums[tid] = s;
    __syncthreads();
    for (int o = 1; o < 1024; o <<= 1) {
        int v = (tid >= o) ? sums[tid - o] : 0;
        __syncthreads();
        sums[tid] += v;
        __syncthreads();
    }
    int run = (tid == 0) ? 0 : sums[tid - 1];
    for (int i = beg; i < end; i++) {
        g_rowptr[i] = run;
        g_cnt[i] = run;
        run += g_deg[i];
    }
    if (tid == 1023) g_rowptr[n] = sums[1023];
}
__global__ void scatter_kernel(const int* __restrict__ src, const int* __restrict__ dst, int e) {
    int i = blockIdx.x * blockDim.x + threadIdx.x;
    if (i < e) {
        int pos = atomicAdd(&g_cnt[dst[i]], 1);
        g_eid[pos] = i;
        g_esrc[pos] = src[i];
    }
}

// ------------------------- fp32 -> bf16 hi/lo split (layer-1 input only) ----------
__global__ void conv_a_kernel(const float* __restrict__ a, int total) {
    int i = blockIdx.x * blockDim.x + threadIdx.x;
    if (i < total) {
        float v = a[i];
        __nv_bfloat16 h = __float2bfloat16(v);
        g_ah[i] = h;
        g_al[i] = __float2bfloat16(v - __bfloat162float(h));
    }
}

// pack W segments [K,256] row-major into bt[NC,K] K-major bf16 hi/lo
__global__ void pack_w_kernel(const float* __restrict__ w0, const float* __restrict__ w1,
                              const float* __restrict__ w2, const float* __restrict__ w3,
                              int K, int NC) {
    int idx = blockIdx.x * blockDim.x + threadIdx.x;
    if (idx >= NC * K) return;
    int nc = idx / K, k = idx - nc * K;
    int seg = nc >> 8, c = nc & 255;
    const float* w = (seg == 0) ? w0 : (seg == 1) ? w1 : (seg == 2) ? w2 : w3;
    float v = w[(size_t)k * 256 + c];
    __nv_bfloat16 h = __float2bfloat16(v);
    g_bth[idx] = h;
    g_btl[idx] = __float2bfloat16(v - __bfloat162float(h));
}

// ------------------------- mma.sync bf16-split GEMM, 128x256 CTA tile -------------------------
#define ATILE 10240
#define BTILE 20480
#define STAGEB (2 * ATILE + 2 * BTILE)
#define GEMM_SMEM (2 * STAGEB)

__global__ __launch_bounds__(256, 1) void mma_gemm_kernel(
    const __nv_bfloat16* __restrict__ ah, const __nv_bfloat16* __restrict__ al,
    const __nv_bfloat16* __restrict__ bth, const __nv_bfloat16* __restrict__ btl,
    const float* __restrict__ b0, const float* __restrict__ b1,
    const float* __restrict__ b2, const float* __restrict__ b3,
    float* __restrict__ o0, float* __restrict__ o1,
    float* __restrict__ o2, float* __restrict__ o3,
    int K)
{
    extern __shared__ __align__(128) char smem[];
    uint32_t sb = smem_u32(smem);
    int tid = threadIdx.x;
    int wid = tid >> 5, lane = tid & 31;
    int seg = blockIdx.x;
    int gRow = blockIdx.y * 128;

    const __nv_bfloat16* aH = ah + (size_t)gRow * K;
    const __nv_bfloat16* aL = al + (size_t)gRow * K;
    const __nv_bfloat16* bH = bth + (size_t)seg * 256 * K;
    const __nv_bfloat16* bL = btl + (size_t)seg * 256 * K;

    int chunks = K >> 5;

    auto load_stage = [&](int c, int s) {
        uint32_t base = sb + s * STAGEB;
        int kc = c << 5;
#pragma unroll
        for (int i = 0; i < 2; i++) {
            int cid = tid + i * 256;
            int r = cid >> 2, ch = cid & 3;
            uint32_t sa = base + r * 80 + ch * 16;
            size_t go = (size_t)r * K + kc + ch * 8;
            cp16(sa, aH + go);
            cp16(sa + ATILE, aL + go);
        }
#pragma unroll
        for (int i = 0; i < 4; i++) {
            int cid = tid + i * 256;
            int r = cid >> 2, ch = cid & 3;
            uint32_t sa = base + 2 * ATILE + r * 80 + ch * 16;
            size_t go = (size_t)r * K + kc + ch * 8;
            cp16(sa, bH + go);
            cp16(sa + BTILE, bL + go);
        }
        CP_COMMIT();
    };

    float acc[4][8][4];
#pragma unroll
    for (int a = 0; a < 4; a++)
#pragma unroll
        for (int b = 0; b < 8; b++)
#pragma unroll
            for (int c = 0; c < 4; c++) acc[a][b][c] = 0.f;

    int warp_m = wid >> 2, warp_n = wid & 3;
    int mrow0 = warp_m * 64, ncol0 = warp_n * 64;
    int lrow = lane & 15, lsel = lane >> 4;
    int bnrow = (lane >> 4) * 8 + (lane & 7);
    int bgk = ((lane >> 3) & 1) * 16;

    load_stage(0, 0);

    for (int c = 0; c < chunks; c++) {
        if (c + 1 < chunks) { load_stage(c + 1, (c + 1) & 1); CP_WAIT(1); }
        else CP_WAIT(0);
        __syncthreads();

        uint32_t base = sb + (c & 1) * STAGEB;
#pragma unroll
        for (int kh = 0; kh < 2; kh++) {
            uint32_t a_h[4][4], a_l[4][4];
#pragma unroll
            for (int mt = 0; mt < 4; mt++) {
                uint32_t ra = base + (mrow0 + mt * 16 + lrow) * 80 + kh * 32 + lsel * 16;
                ldm_x4(a_h[mt], ra);
                ldm_x4(a_l[mt], ra + ATILE);
            }
#pragma unroll
            for (int ntp = 0; ntp < 4; ntp++) {
                uint32_t b_h[4], b_l[4];
                uint32_t rb = base + 2 * ATILE + (ncol0 + ntp * 16 + bnrow) * 80 + kh * 32 + bgk;
                ldm_x4(b_h, rb);
                ldm_x4(b_l, rb + BTILE);
#pragma unroll
                for (int mt = 0; mt < 4; mt++) {
                    mma_bf16(acc[mt][2 * ntp],     a_h[mt], b_h);
                    mma_bf16(acc[mt][2 * ntp],     a_h[mt], b_l);
                    mma_bf16(acc[mt][2 * ntp],     a_l[mt], b_h);
                    mma_bf16(acc[mt][2 * ntp + 1], a_h[mt], b_h + 2);
                    mma_bf16(acc[mt][2 * ntp + 1], a_h[mt], b_l + 2);
                    mma_bf16(acc[mt][2 * ntp + 1], a_l[mt], b_h + 2);
                }
            }
        }
        __syncthreads();
    }

    const float* bias = (seg == 0) ? b0 : (seg == 1) ? b1 : (seg == 2) ? b2 : b3;
    float* out = (seg == 0) ? o0 : (seg == 1) ? o1 : (seg == 2) ? o2 : o3;
    int colBase = ncol0 + (lane & 3) * 2;
    int row0 = gRow + mrow0 + (lane >> 2);
#pragma unroll
    for (int mt = 0; mt < 4; mt++) {
        int row = row0 + mt * 16;
#pragma unroll
        for (int nt = 0; nt < 8; nt++) {
            int col = colBase + nt * 8;
            float bv0 = bias[col], bv1 = bias[col + 1];
            float2 v0 = make_float2(acc[mt][nt][0] + bv0, acc[mt][nt][1] + bv1);
            float2 v1 = make_float2(acc[mt][nt][2] + bv0, acc[mt][nt][3] + bv1);
            *(float2*)(out + (size_t)row * 256 + col) = v0;
            *(float2*)(out + (size_t)(row + 8) * 256 + col) = v1;
        }
    }
}

// ------------------------- p[n][h*32+d] = sum_c q[n][h*32+c] * we[d][h*32+c] -------------------------
__global__ __launch_bounds__(256) void compute_p_kernel(
    const float* __restrict__ q, const float* __restrict__ we,
    float* __restrict__ p, int M)
{
    __shared__ float wet[256 * 33];
    __shared__ float qs[8][256];
    int tid = threadIdx.x;
    for (int i = tid; i < 8192; i += 256) {
        int d = i >> 8, col = i & 255;
        wet[col * 33 + d] = we[i];
    }
    int base = blockIdx.x * 8;
    for (int i = 0; i < 8; i++) {
        int n = base + i;
        qs[i][tid] = (n < M) ? q[(size_t)n * 256 + tid] : 0.f;
    }
    __syncthreads();
    int h = tid >> 5, d = tid & 31;
    for (int i = 0; i < 8; i++) {
        int n = base + i;
        if (n >= M) break;
        float s = 0.f;
#pragma unroll
        for (int c = 0; c < 32; c++)
            s += qs[i][h * 32 + c] * wet[(h * 32 + c) * 33 + d];
        p[(size_t)n * 256 + h * 32 + d] = s;
    }
}

// ------------------------- edge attention: one warp per destination node (lean, no smem) -------
// direct-exp softmax: logits are O(1) dots, exp safe in fp32, normalized alpha identical.
__global__ __launch_bounds__(256) void edge_attn_kernel(
    const float* __restrict__ qg, const float* __restrict__ kg,
    const float* __restrict__ vg, const float* __restrict__ pg,
    const float* __restrict__ ea,
    float* __restrict__ attn, float* __restrict__ accea, int M)
{
    int warpid = (blockIdx.x * blockDim.x + threadIdx.x) >> 5;
    if (warpid >= M) return;
    int lane = threadIdx.x & 31;
    int chunk = lane & 3;
    int off = lane << 3;
    size_t nb = (size_t)warpid * 256;

    float4 qa = *(const float4*)(qg + nb + off);
    float4 qb = *(const float4*)(qg + nb + off + 4);
    float4 pa = *(const float4*)(pg + nb + off);
    float4 pb = *(const float4*)(pg + nb + off + 4);

    int beg = g_rowptr[warpid], end = g_rowptr[warpid + 1];
    float denom = 0.f;
    float ac0 = 0, ac1 = 0, ac2 = 0, ac3 = 0, ac4 = 0, ac5 = 0, ac6 = 0, ac7 = 0;
    float ae0 = 0, ae1 = 0, ae2 = 0, ae3 = 0, ae4 = 0, ae5 = 0, ae6 = 0, ae7 = 0;

    for (int j = beg; j < end; j++) {
        int e = g_eid[j];
        int s = g_esrc[j];
        size_t sbv = (size_t)s * 256;
        size_t eb = (size_t)e * 32 + (chunk << 3);
        float4 ka = *(const float4*)(kg + sbv + off);
        float4 kb = *(const float4*)(kg + sbv + off + 4);
        float4 aa = *(const float4*)(ea + eb);
        float4 ab = *(const float4*)(ea + eb + 4);
        float part = qa.x * ka.x + qa.y * ka.y + qa.z * ka.z + qa.w * ka.w
                   + qb.x * kb.x + qb.y * kb.y + qb.z * kb.z + qb.w * kb.w
                   + pa.x * aa.x + pa.y * aa.y + pa.z * aa.z + pa.w * aa.w
                   + pb.x * ab.x + pb.y * ab.y + pb.z * ab.z + pb.w * ab.w;
        part += __shfl_xor_sync(0xffffffffu, part, 1);
        part += __shfl_xor_sync(0xffffffffu, part, 2);
        float ex = __expf(part * 0.17677669529663687f);

        float4 va = *(const float4*)(vg + sbv + off);
        float4 vb = *(const float4*)(vg + sbv + off + 4);

        denom += ex;
        ac0 = fmaf(ex, va.x, ac0);  ac1 = fmaf(ex, va.y, ac1);
        ac2 = fmaf(ex, va.z, ac2);  ac3 = fmaf(ex, va.w, ac3);
        ac4 = fmaf(ex, vb.x, ac4);  ac5 = fmaf(ex, vb.y, ac5);
        ac6 = fmaf(ex, vb.z, ac6);  ac7 = fmaf(ex, vb.w, ac7);
        ae0 = fmaf(ex, aa.x, ae0);  ae1 = fmaf(ex, aa.y, ae1);
        ae2 = fmaf(ex, aa.z, ae2);  ae3 = fmaf(ex, aa.w, ae3);
        ae4 = fmaf(ex, ab.x, ae4);  ae5 = fmaf(ex, ab.y, ae5);
        ae6 = fmaf(ex, ab.z, ae6);  ae7 = fmaf(ex, ab.w, ae7);
    }

    float inv = 1.f / (denom + 1e-16f);
    *(float4*)(attn + nb + off)      = make_float4(ac0 * inv, ac1 * inv, ac2 * inv, ac3 * inv);
    *(float4*)(attn + nb + off + 4)  = make_float4(ac4 * inv, ac5 * inv, ac6 * inv, ac7 * inv);
    *(float4*)(accea + nb + off)     = make_float4(ae0 * inv, ae1 * inv, ae2 * inv, ae3 * inv);
    *(float4*)(accea + nb + off + 4) = make_float4(ae4 * inv, ae5 * inv, ae6 * inv, ae7 * inv);
}

// ------------------------- layer-1 epilogue (+ bf16 hi/lo split of h) -------------------------
__global__ __launch_bounds__(256) void post1_kernel(
    const float* __restrict__ attn, const float* __restrict__ accea,
    const float* __restrict__ we, const float* __restrict__ skip,
    const float* __restrict__ g, const float* __restrict__ b,
    float* __restrict__ hout, __nv_bfloat16* __restrict__ ahout,
    __nv_bfloat16* __restrict__ alout, int M)
{
    __shared__ float ws[8192];
    __shared__ float accs[256];
    __shared__ float red1[8], red2[8];
    int tid = threadIdx.x;
    for (int i = tid; i < 8192; i += 256) ws[i] = we[i];
    float gg = g[tid], bb = b[tid];
    int h = tid >> 5, lane = tid & 31;
    int base = blockIdx.x * 8;
    for (int i = 0; i < 8; i++) {
        int n = base + i;
        if (n >= M) break;
        __syncthreads();
        accs[tid] = accea[(size_t)n * 256 + tid];
        __syncthreads();
        float extra = 0.f;
#pragma unroll
        for (int d = 0; d < 32; d++) extra += accs[h * 32 + d] * ws[d * 256 + tid];
        float val = attn[(size_t)n * 256 + tid] + extra + skip[(size_t)n * 256 + tid];
        val = fmaxf(val, 0.f);
        float s1 = val, s2 = val * val;
#pragma unroll
        for (int o = 16; o > 0; o >>= 1) {
            s1 += __shfl_xor_sync(0xffffffffu, s1, o);
            s2 += __shfl_xor_sync(0xffffffffu, s2, o);
        }
        if (lane == 0) { red1[h] = s1; red2[h] = s2; }
        __syncthreads();
        float t1 = 0.f, t2 = 0.f;
#pragma unroll
        for (int w = 0; w < 8; w++) { t1 += red1[w]; t2 += red2[w]; }
        float mu = t1 * (1.f / 256.f);
        float var = t2 * (1.f / 256.f) - mu * mu;
        float inv = rsqrtf(var + 1e-5f);
        float ov = (val - mu) * inv * gg + bb;
        hout[(size_t)n * 256 + tid] = ov;
        __nv_bfloat16 hi = __float2bfloat16(ov);
        ahout[(size_t)n * 256 + tid] = hi;
        alout[(size_t)n * 256 + tid] = __float2bfloat16(ov - __bfloat162float(hi));
    }
}

// ------------------------- skip2: out[N,32] = h[N,256] @ w[256,32] + b -------------------------
__global__ __launch_bounds__(256) void skip2_kernel(
    const float* __restrict__ hin, const float* __restrict__ w,
    const float* __restrict__ b, float* __restrict__ out, int M)
{
    __shared__ float ws[8192];
    __shared__ float xs[8][256];
    int tid = threadIdx.x;
    for (int i = tid; i < 8192; i += 256) ws[i] = w[i];
    int base = blockIdx.x * 8;
    for (int i = 0; i < 8; i++) {
        int n = base + i;
        xs[i][tid] = (n < M) ? hin[(size_t)n * 256 + tid] : 0.f;
    }
    __syncthreads();
    int r = tid >> 5, c = tid & 31;
    float s = b[c];
#pragma unroll 8
    for (int k = 0; k < 256; k++) s += xs[r][k] * ws[k * 32 + c];
    int n = base + r;
    if (n < M) out[(size_t)n * 32 + c] = s;
}

// ------------------------- layer-2 epilogue -------------------------
__global__ __launch_bounds__(256) void post2_kernel(
    const float* __restrict__ attn, const float* __restrict__ accea,
    const float* __restrict__ we, const float* __restrict__ skip2,
    const float* __restrict__ wc, const float* __restrict__ bc,
    float* __restrict__ out, int M)
{
    __shared__ float ws[8192];
    __shared__ float accs[256];
    __shared__ float vals[264];
    int tid = threadIdx.x;
    for (int i = tid; i < 8192; i += 256) ws[i] = we[i];
    int h = tid >> 5, lane = tid & 31;
    int base = blockIdx.x * 8;
    for (int i = 0; i < 8; i++) {
        int n = base + i;
        if (n >= M) break;
        __syncthreads();
        accs[tid] = accea[(size_t)n * 256 + tid];
        __syncthreads();
        float extra = 0.f;
#pragma unroll
        for (int d = 0; d < 32; d++) extra += accs[h * 32 + d] * ws[d * 256 + tid];
        vals[h * 33 + lane] = attn[(size_t)n * 256 + tid] + extra;
        __syncthreads();
        if (tid < 32) {
            float s = 0.f;
#pragma unroll
            for (int hh = 0; hh < 8; hh++) s += vals[hh * 33 + tid];
            float z = fmaxf(s * 0.125f + skip2[(size_t)n * 32 + tid], 0.f);
            float d0 = z * wc[tid * 2 + 0];
            float d1 = z * wc[tid * 2 + 1];
#pragma unroll
            for (int o = 16; o > 0; o >>= 1) {
                d0 += __shfl_xor_sync(0xffffffffu, d0, o);
                d1 += __shfl_xor_sync(0xffffffffu, d1, o);
            }
            if (tid == 0) {
                out[(size_t)n * 2 + 0] = d0 + bc[0];
                out[(size_t)n * 2 + 1] = d1 + bc[1];
            }
        }
    }
}

// ------------------------- launcher -------------------------
extern "C" void kernel_launch(void* const* d_in, const int* in_sizes, int n_in,
                              void* d_out, int out_size)
{
    const float* x      = (const float*)d_in[0];
    const int*   eidx   = (const int*)d_in[1];
    const float* eattr  = (const float*)d_in[2];
    const float* wq1    = (const float*)d_in[3];
    const float* bq1    = (const float*)d_in[4];
    const float* wk1    = (const float*)d_in[5];
    const float* bk1    = (const float*)d_in[6];
    const float* wv1    = (const float*)d_in[7];
    const float* bv1    = (const float*)d_in[8];
    const float* we1    = (const float*)d_in[9];
    const float* wskip1 = (const float*)d_in[10];
    const float* bskip1 = (const float*)d_in[11];
    const float* g1     = (const float*)d_in[12];
    const float* b1     = (const float*)d_in[13];
    const float* wq2    = (const float*)d_in[14];
    const float* bq2    = (const float*)d_in[15];
    const float* wk2    = (const float*)d_in[16];
    const float* bk2    = (const float*)d_in[17];
    const float* wv2    = (const float*)d_in[18];
    const float* bv2    = (const float*)d_in[19];
    const float* we2    = (const float*)d_in[20];
    const float* wskip2 = (const float*)d_in[21];
    const float* bskip2 = (const float*)d_in[22];
    const float* wc     = (const float*)d_in[23];
    const float* bc     = (const float*)d_in[24];

    int n = in_sizes[0] / 128;
    int e = in_sizes[1] / 2;
    const int* src = eidx;
    const int* dst = eidx + e;

    float *pq, *pk, *pv, *pp, *ps1, *pattn, *pacc, *ph, *ps2;
    __nv_bfloat16 *pah, *pal, *pbh, *pbl;
    cudaGetSymbolAddress((void**)&pq, g_q);
    cudaGetSymbolAddress((void**)&pk, g_k);
    cudaGetSymbolAddress((void**)&pv, g_v);
    cudaGetSymbolAddress((void**)&pp, g_p);
    cudaGetSymbolAddress((void**)&ps1, g_skip1);
    cudaGetSymbolAddress((void**)&pattn, g_attn);
    cudaGetSymbolAddress((void**)&pacc, g_accea);
    cudaGetSymbolAddress((void**)&ph, g_h);
    cudaGetSymbolAddress((void**)&ps2, g_skip2);
    cudaGetSymbolAddress((void**)&pah, g_ah);
    cudaGetSymbolAddress((void**)&pal, g_al);
    cudaGetSymbolAddress((void**)&pbh, g_bth);
    cudaGetSymbolAddress((void**)&pbl, g_btl);

    cudaFuncSetAttribute(mma_gemm_kernel,
                         cudaFuncAttributeMaxDynamicSharedMemorySize, GEMM_SMEM);

    int nb256 = (n + 255) / 256;
    int eb256 = (e + 255) / 256;
    int nodeBlocks = (n + 7) / 8;
    int mTiles = (n + 127) / 128;

    // Layer-1 projections (mma_gemm at launch index 3 for the ncu window)
    conv_a_kernel<<<(n * 128 + 255) / 256, 256>>>(x, n * 128);
    pack_w_kernel<<<(1024 * 128 + 255) / 256, 256>>>(wq1, wk1, wv1, wskip1, 128, 1024);
    zero_deg_kernel<<<nb256, 256>>>(n);
    {
        dim3 grid(4, mTiles);
        mma_gemm_kernel<<<grid, 256, GEMM_SMEM>>>(pah, pal, pbh, pbl,
                                                  bq1, bk1, bv1, bskip1,
                                                  pq, pk, pv, ps1, 128);
    }
    hist_kernel<<<eb256, 256>>>(dst, e);
    scan_kernel<<<1, 1024>>>(n);
    scatter_kernel<<<eb256, 256>>>(src, dst, e);

    compute_p_kernel<<<nodeBlocks, 256>>>(pq, we1, pp, n);
    edge_attn_kernel<<<nodeBlocks, 256>>>(pq, pk, pv, pp, eattr, pattn, pacc, n);
    post1_kernel<<<nodeBlocks, 256>>>(pattn, pacc, we1, ps1, g1, b1, ph, pah, pal, n);

    // Layer 2 (pah/pal already produced by post1)
    pack_w_kernel<<<(768 * 256 + 255) / 256, 256>>>(wq2, wk2, wv2, wv2, 256, 768);
    {
        dim3 grid(3, mTiles);
        mma_gemm_kernel<<<grid, 256, GEMM_SMEM>>>(pah, pal, pbh, pbl,
                                                  bq2, bk2, bv2, bv2,
                                                  pq, pk, pv, pv, 256);
    }
    skip2_kernel<<<nodeBlocks, 256>>>(ph, wskip2, bskip2, ps2, n);
    compute_p_kernel<<<nodeBlocks, 256>>>(pq, we2, pp, n);
    edge_attn_kernel<<<nodeBlocks, 256>>>(pq, pk, pv, pp, eattr, pattn, pacc, n);
    post2_kernel<<<nodeBlocks, 256>>>(pattn, pacc, we2, ps2, wc, bc, (float*)d_out, n);
}

// round 12
// speedup vs baseline: 1.1063x; 1.1063x over previous
#include <cuda_runtime.h>
#include <cuda_bf16.h>
#include <math.h>
#include <stdint.h>

#define NMAX 50000
#define NPAD 50048   // 391 * 128
#define EMAX 400000
#define HS2 1028     // per-head stride in W2 smem (conflict-free: 1028 % 32 == 4)

// ------------------------- scratch (static device memory) -------------------------
__device__ float g_q[(size_t)NPAD * 256];
__device__ float g_k[(size_t)NPAD * 256];
__device__ float g_v[(size_t)NPAD * 256];
__device__ float g_p[(size_t)NPAD * 256];
__device__ float g_skip1[(size_t)NPAD * 256];
__device__ float g_h[(size_t)NPAD * 256];
__device__ float g_skip2[(size_t)NPAD * 32];
__device__ __nv_bfloat16 g_ah[(size_t)NPAD * 256];
__device__ __nv_bfloat16 g_al[(size_t)NPAD * 256];
__device__ __nv_bfloat16 g_bth[1024 * 256];
__device__ __nv_bfloat16 g_btl[1024 * 256];
__device__ int g_deg[NMAX];
__device__ int g_rowptr[NMAX + 1];
__device__ int g_cnt[NMAX];
__device__ int g_eid[EMAX];

// ------------------------- PTX helpers -------------------------
__device__ __forceinline__ uint32_t smem_u32(const void* p) {
    uint32_t a;
    asm("{ .reg .u64 t; cvta.to.shared.u64 t, %1; cvt.u32.u64 %0, t; }" : "=r"(a) : "l"(p));
    return a;
}
__device__ __forceinline__ void cp16(uint32_t saddr, const void* gaddr) {
    asm volatile("cp.async.cg.shared.global [%0], [%1], 16;" :: "r"(saddr), "l"(gaddr) : "memory");
}
#define CP_COMMIT() asm volatile("cp.async.commit_group;" ::: "memory")
#define CP_WAIT(N)  asm volatile("cp.async.wait_group %0;" :: "n"(N) : "memory")

__device__ __forceinline__ void ldm_x4(uint32_t* r, uint32_t addr) {
    asm volatile("ldmatrix.sync.aligned.m8n8.x4.shared.b16 {%0,%1,%2,%3}, [%4];"
        : "=r"(r[0]), "=r"(r[1]), "=r"(r[2]), "=r"(r[3]) : "r"(addr));
}
__device__ __forceinline__ void mma_bf16(float* c, const uint32_t* a, const uint32_t* b) {
    asm volatile("mma.sync.aligned.m16n8k16.row.col.f32.bf16.bf16.f32 "
        "{%0,%1,%2,%3}, {%4,%5,%6,%7}, {%8,%9}, {%0,%1,%2,%3};"
        : "+f"(c[0]), "+f"(c[1]), "+f"(c[2]), "+f"(c[3])
        : "r"(a[0]), "r"(a[1]), "r"(a[2]), "r"(a[3]), "r"(b[0]), "r"(b[1]));
}

// ------------------------- CSR build -------------------------
__global__ void zero_deg_kernel(int n) {
    int i = blockIdx.x * blockDim.x + threadIdx.x;
    if (i < n) g_deg[i] = 0;
}
__global__ void hist_kernel(const int* __restrict__ dst, int e) {
    int i = blockIdx.x * blockDim.x + threadIdx.x;
    if (i < e) atomicAdd(&g_deg[dst[i]], 1);
}
__global__ void scan_kernel(int n) {
    __shared__ int sums[1024];
    int tid = threadIdx.x;
    int per = (n + 1023) >> 10;
    int beg = tid * per;
    int end = min(beg + per, n);
    int s = 0;
    for (int i = beg; i < end; i++) s += g_deg[i];
    sums[tid] = s;
    __syncthreads();
    for (int o = 1; o < 1024; o <<= 1) {
        int v = (tid >= o) ? sums[tid - o] : 0;
        __syncthreads();
        sums[tid] += v;
        __syncthreads();
    }
    int run = (tid == 0) ? 0 : sums[tid - 1];
    for (int i = beg; i < end; i++) {
        g_rowptr[i] = run;
        g_cnt[i] = run;
        run += g_deg[i];
    }
    if (tid == 1023) g_rowptr[n] = sums[1023];
}
__global__ void scatter_kernel(const int* __restrict__ dst, int e) {
    int i = blockIdx.x * blockDim.x + threadIdx.x;
    if (i < e) {
        int pos = atomicAdd(&g_cnt[dst[i]], 1);
        g_eid[pos] = i;
    }
}

// ------------------------- fp32 -> bf16 hi/lo split (layer-1 input only) ----------
__global__ void conv_a_kernel(const float* __restrict__ a, int total) {
    int i = blockIdx.x * blockDim.x + threadIdx.x;
    if (i < total) {
        float v = a[i];
        __nv_bfloat16 h = __float2bfloat16(v);
        g_ah[i] = h;
        g_al[i] = __float2bfloat16(v - __bfloat162float(h));
    }
}

// pack W segments [K,256] row-major into bt[NC,K] K-major bf16 hi/lo
__global__ void pack_w_kernel(const float* __restrict__ w0, const float* __restrict__ w1,
                              const float* __restrict__ w2, const float* __restrict__ w3,
                              int K, int NC) {
    int idx = blockIdx.x * blockDim.x + threadIdx.x;
    if (idx >= NC * K) return;
    int nc = idx / K, k = idx - nc * K;
    int seg = nc >> 8, c = nc & 255;
    const float* w = (seg == 0) ? w0 : (seg == 1) ? w1 : (seg == 2) ? w2 : w3;
    float v = w[(size_t)k * 256 + c];
    __nv_bfloat16 h = __float2bfloat16(v);
    g_bth[idx] = h;
    g_btl[idx] = __float2bfloat16(v - __bfloat162float(h));
}

// ------------------------- mma.sync bf16-split GEMM, 128x256 CTA tile -------------------------
#define ATILE 10240
#define BTILE 20480
#define STAGEB (2 * ATILE + 2 * BTILE)
#define GEMM_SMEM (2 * STAGEB)

__global__ __launch_bounds__(256, 1) void mma_gemm_kernel(
    const __nv_bfloat16* __restrict__ ah, const __nv_bfloat16* __restrict__ al,
    const __nv_bfloat16* __restrict__ bth, const __nv_bfloat16* __restrict__ btl,
    const float* __restrict__ b0, const float* __restrict__ b1,
    const float* __restrict__ b2, const float* __restrict__ b3,
    float* __restrict__ o0, float* __restrict__ o1,
    float* __restrict__ o2, float* __restrict__ o3,
    int K)
{
    extern __shared__ __align__(128) char smem[];
    uint32_t sb = smem_u32(smem);
    int tid = threadIdx.x;
    int wid = tid >> 5, lane = tid & 31;
    int seg = blockIdx.x;
    int gRow = blockIdx.y * 128;

    const __nv_bfloat16* aH = ah + (size_t)gRow * K;
    const __nv_bfloat16* aL = al + (size_t)gRow * K;
    const __nv_bfloat16* bH = bth + (size_t)seg * 256 * K;
    const __nv_bfloat16* bL = btl + (size_t)seg * 256 * K;

    int chunks = K >> 5;

    auto load_stage = [&](int c, int s) {
        uint32_t base = sb + s * STAGEB;
        int kc = c << 5;
#pragma unroll
        for (int i = 0; i < 2; i++) {
            int cid = tid + i * 256;
            int r = cid >> 2, ch = cid & 3;
            uint32_t sa = base + r * 80 + ch * 16;
            size_t go = (size_t)r * K + kc + ch * 8;
            cp16(sa, aH + go);
            cp16(sa + ATILE, aL + go);
        }
#pragma unroll
        for (int i = 0; i < 4; i++) {
            int cid = tid + i * 256;
            int r = cid >> 2, ch = cid & 3;
            uint32_t sa = base + 2 * ATILE + r * 80 + ch * 16;
            size_t go = (size_t)r * K + kc + ch * 8;
            cp16(sa, bH + go);
            cp16(sa + BTILE, bL + go);
        }
        CP_COMMIT();
    };

    float acc[4][8][4];
#pragma unroll
    for (int a = 0; a < 4; a++)
#pragma unroll
        for (int b = 0; b < 8; b++)
#pragma unroll
            for (int c = 0; c < 4; c++) acc[a][b][c] = 0.f;

    int warp_m = wid >> 2, warp_n = wid & 3;
    int mrow0 = warp_m * 64, ncol0 = warp_n * 64;
    int lrow = lane & 15, lsel = lane >> 4;
    int bnrow = (lane >> 4) * 8 + (lane & 7);
    int bgk = ((lane >> 3) & 1) * 16;

    load_stage(0, 0);

    for (int c = 0; c < chunks; c++) {
        if (c + 1 < chunks) { load_stage(c + 1, (c + 1) & 1); CP_WAIT(1); }
        else CP_WAIT(0);
        __syncthreads();

        uint32_t base = sb + (c & 1) * STAGEB;
#pragma unroll
        for (int kh = 0; kh < 2; kh++) {
            uint32_t a_h[4][4], a_l[4][4];
#pragma unroll
            for (int mt = 0; mt < 4; mt++) {
                uint32_t ra = base + (mrow0 + mt * 16 + lrow) * 80 + kh * 32 + lsel * 16;
                ldm_x4(a_h[mt], ra);
                ldm_x4(a_l[mt], ra + ATILE);
            }
#pragma unroll
            for (int ntp = 0; ntp < 4; ntp++) {
                uint32_t b_h[4], b_l[4];
                uint32_t rb = base + 2 * ATILE + (ncol0 + ntp * 16 + bnrow) * 80 + kh * 32 + bgk;
                ldm_x4(b_h, rb);
                ldm_x4(b_l, rb + BTILE);
#pragma unroll
                for (int mt = 0; mt < 4; mt++) {
                    mma_bf16(acc[mt][2 * ntp],     a_h[mt], b_h);
                    mma_bf16(acc[mt][2 * ntp],     a_h[mt], b_l);
                    mma_bf16(acc[mt][2 * ntp],     a_l[mt], b_h);
                    mma_bf16(acc[mt][2 * ntp + 1], a_h[mt], b_h + 2);
                    mma_bf16(acc[mt][2 * ntp + 1], a_h[mt], b_l + 2);
                    mma_bf16(acc[mt][2 * ntp + 1], a_l[mt], b_h + 2);
                }
            }
        }
        __syncthreads();
    }

    const float* bias = (seg == 0) ? b0 : (seg == 1) ? b1 : (seg == 2) ? b2 : b3;
    float* out = (seg == 0) ? o0 : (seg == 1) ? o1 : (seg == 2) ? o2 : o3;
    int colBase = ncol0 + (lane & 3) * 2;
    int row0 = gRow + mrow0 + (lane >> 2);
#pragma unroll
    for (int mt = 0; mt < 4; mt++) {
        int row = row0 + mt * 16;
#pragma unroll
        for (int nt = 0; nt < 8; nt++) {
            int col = colBase + nt * 8;
            float bv0 = bias[col], bv1 = bias[col + 1];
            float2 v0 = make_float2(acc[mt][nt][0] + bv0, acc[mt][nt][1] + bv1);
            float2 v1 = make_float2(acc[mt][nt][2] + bv0, acc[mt][nt][3] + bv1);
            *(float2*)(out + (size_t)row * 256 + col) = v0;
            *(float2*)(out + (size_t)(row + 8) * 256 + col) = v1;
        }
    }
}

// ------------------------- p[n][h*32+d] = sum_c q[n][h*32+c] * we[d][h*32+c] -------------------------
__global__ __launch_bounds__(256) void compute_p_kernel(
    const float* __restrict__ q, const float* __restrict__ we,
    float* __restrict__ p, int M)
{
    __shared__ float wet[256 * 33];
    __shared__ float qs[8][256];
    int tid = threadIdx.x;
    for (int i = tid; i < 8192; i += 256) {
        int d = i >> 8, col = i & 255;
        wet[col * 33 + d] = we[i];
    }
    int base = blockIdx.x * 8;
    for (int i = 0; i < 8; i++) {
        int n = base + i;
        qs[i][tid] = (n < M) ? q[(size_t)n * 256 + tid] : 0.f;
    }
    __syncthreads();
    int h = tid >> 5, d = tid & 31;
    for (int i = 0; i < 8; i++) {
        int n = base + i;
        if (n >= M) break;
        float s = 0.f;
#pragma unroll
        for (int c = 0; c < 32; c++)
            s += qs[i][h * 32 + c] * wet[(h * 32 + c) * 33 + d];
        p[(size_t)n * 256 + h * 32 + d] = s;
    }
}

// ============== fused edge attention + epilogue, LAYER 1 ==============
// One warp per dst node: direct-exp softmax gather, then extra=accea@we,
// +skip, relu, LayerNorm -> h (fp32) + bf16 hi/lo split for layer-2 GEMM.
__global__ __launch_bounds__(256) void fused_attn1_kernel(
    const float* __restrict__ qg, const float* __restrict__ kg,
    const float* __restrict__ vg, const float* __restrict__ pg,
    const int* __restrict__ src, const float* __restrict__ ea,
    const float* __restrict__ we, const float* __restrict__ skip,
    const float* __restrict__ g, const float* __restrict__ b,
    float* __restrict__ hout, __nv_bfloat16* __restrict__ ahout,
    __nv_bfloat16* __restrict__ alout, int M)
{
    __shared__ __align__(16) float W2[8224];    // [h][d][t] head-stride 1028
    __shared__ float stage[8][264];             // per-warp accea staging (33-padded)
    __shared__ float gsh[256], bsh[256];
    int tid = threadIdx.x;
    for (int i = tid; i < 8192; i += 256) {
        int d = i >> 8, col = i & 255;
        W2[(col >> 5) * HS2 + d * 32 + (col & 31)] = we[i];
    }
    gsh[tid] = g[tid];
    bsh[tid] = b[tid];
    __syncthreads();

    int wid = tid >> 5, lane = tid & 31;
    int n = blockIdx.x * 8 + wid;
    if (n >= M) return;
    int h = lane >> 2, chunk = lane & 3, off = lane << 3;
    size_t nb = (size_t)n * 256;

    float4 qa = *(const float4*)(qg + nb + off);
    float4 qb = *(const float4*)(qg + nb + off + 4);
    float4 pa = *(const float4*)(pg + nb + off);
    float4 pb = *(const float4*)(pg + nb + off + 4);

    int beg = g_rowptr[n], end = g_rowptr[n + 1];
    float denom = 0.f;
    float ac0 = 0, ac1 = 0, ac2 = 0, ac3 = 0, ac4 = 0, ac5 = 0, ac6 = 0, ac7 = 0;
    float ae0 = 0, ae1 = 0, ae2 = 0, ae3 = 0, ae4 = 0, ae5 = 0, ae6 = 0, ae7 = 0;

    for (int j = beg; j < end; j++) {
        int e = g_eid[j];
        int s = src[e];
        size_t sbv = (size_t)s * 256;
        size_t eb = (size_t)e * 32 + (chunk << 3);
        float4 ka = *(const float4*)(kg + sbv + off);
        float4 kb = *(const float4*)(kg + sbv + off + 4);
        float4 aa = *(const float4*)(ea + eb);
        float4 ab = *(const float4*)(ea + eb + 4);
        float part = qa.x * ka.x + qa.y * ka.y + qa.z * ka.z + qa.w * ka.w
                   + qb.x * kb.x + qb.y * kb.y + qb.z * kb.z + qb.w * kb.w
                   + pa.x * aa.x + pa.y * aa.y + pa.z * aa.z + pa.w * aa.w
                   + pb.x * ab.x + pb.y * ab.y + pb.z * ab.z + pb.w * ab.w;
        part += __shfl_xor_sync(0xffffffffu, part, 1);
        part += __shfl_xor_sync(0xffffffffu, part, 2);
        float ex = __expf(part * 0.17677669529663687f);

        float4 va = *(const float4*)(vg + sbv + off);
        float4 vb = *(const float4*)(vg + sbv + off + 4);

        denom += ex;
        ac0 = fmaf(ex, va.x, ac0);  ac1 = fmaf(ex, va.y, ac1);
        ac2 = fmaf(ex, va.z, ac2);  ac3 = fmaf(ex, va.w, ac3);
        ac4 = fmaf(ex, vb.x, ac4);  ac5 = fmaf(ex, vb.y, ac5);
        ac6 = fmaf(ex, vb.z, ac6);  ac7 = fmaf(ex, vb.w, ac7);
        ae0 = fmaf(ex, aa.x, ae0);  ae1 = fmaf(ex, aa.y, ae1);
        ae2 = fmaf(ex, aa.z, ae2);  ae3 = fmaf(ex, aa.w, ae3);
        ae4 = fmaf(ex, ab.x, ae4);  ae5 = fmaf(ex, ab.y, ae5);
        ae6 = fmaf(ex, ab.z, ae6);  ae7 = fmaf(ex, ab.w, ae7);
    }

    float inv = 1.f / (denom + 1e-16f);
    // stage accea (normalized) at [h*33 + d] (bank-spread across heads)
    float* st = stage[wid];
    int sbase = h * 33 + chunk * 8;
    st[sbase + 0] = ae0 * inv; st[sbase + 1] = ae1 * inv;
    st[sbase + 2] = ae2 * inv; st[sbase + 3] = ae3 * inv;
    st[sbase + 4] = ae4 * inv; st[sbase + 5] = ae5 * inv;
    st[sbase + 6] = ae6 * inv; st[sbase + 7] = ae7 * inv;
    __syncwarp();

    // extra = accea @ we for this lane's 8 cols
    float4 e0 = make_float4(0.f, 0.f, 0.f, 0.f);
    float4 e1 = make_float4(0.f, 0.f, 0.f, 0.f);
    const float* wb = &W2[h * HS2 + chunk * 8];
#pragma unroll
    for (int d = 0; d < 32; d++) {
        float av = st[h * 33 + d];
        float4 w0 = *(const float4*)(wb + d * 32);
        float4 w1 = *(const float4*)(wb + d * 32 + 4);
        e0.x += av * w0.x; e0.y += av * w0.y; e0.z += av * w0.z; e0.w += av * w0.w;
        e1.x += av * w1.x; e1.y += av * w1.y; e1.z += av * w1.z; e1.w += av * w1.w;
    }

    float4 sk0 = *(const float4*)(skip + nb + off);
    float4 sk1 = *(const float4*)(skip + nb + off + 4);
    float v0 = fmaxf(ac0 * inv + e0.x + sk0.x, 0.f);
    float v1 = fmaxf(ac1 * inv + e0.y + sk0.y, 0.f);
    float v2 = fmaxf(ac2 * inv + e0.z + sk0.z, 0.f);
    float v3 = fmaxf(ac3 * inv + e0.w + sk0.w, 0.f);
    float v4 = fmaxf(ac4 * inv + e1.x + sk1.x, 0.f);
    float v5 = fmaxf(ac5 * inv + e1.y + sk1.y, 0.f);
    float v6 = fmaxf(ac6 * inv + e1.z + sk1.z, 0.f);
    float v7 = fmaxf(ac7 * inv + e1.w + sk1.w, 0.f);

    float s1 = v0 + v1 + v2 + v3 + v4 + v5 + v6 + v7;
    float s2 = v0 * v0 + v1 * v1 + v2 * v2 + v3 * v3 + v4 * v4 + v5 * v5 + v6 * v6 + v7 * v7;
#pragma unroll
    for (int o = 16; o > 0; o >>= 1) {
        s1 += __shfl_xor_sync(0xffffffffu, s1, o);
        s2 += __shfl_xor_sync(0xffffffffu, s2, o);
    }
    float mu = s1 * (1.f / 256.f);
    float var = s2 * (1.f / 256.f) - mu * mu;
    float rinv = rsqrtf(var + 1e-5f);

    float o0 = (v0 - mu) * rinv * gsh[off + 0] + bsh[off + 0];
    float o1 = (v1 - mu) * rinv * gsh[off + 1] + bsh[off + 1];
    float o2 = (v2 - mu) * rinv * gsh[off + 2] + bsh[off + 2];
    float o3 = (v3 - mu) * rinv * gsh[off + 3] + bsh[off + 3];
    float o4 = (v4 - mu) * rinv * gsh[off + 4] + bsh[off + 4];
    float o5 = (v5 - mu) * rinv * gsh[off + 5] + bsh[off + 5];
    float o6 = (v6 - mu) * rinv * gsh[off + 6] + bsh[off + 6];
    float o7 = (v7 - mu) * rinv * gsh[off + 7] + bsh[off + 7];

    *(float4*)(hout + nb + off)     = make_float4(o0, o1, o2, o3);
    *(float4*)(hout + nb + off + 4) = make_float4(o4, o5, o6, o7);

    // bf16 hi/lo split for layer-2 GEMM operand
    float ov[8] = {o0, o1, o2, o3, o4, o5, o6, o7};
    __nv_bfloat16 hi[8];
    __nv_bfloat16 lo[8];
#pragma unroll
    for (int j = 0; j < 8; j++) {
        hi[j] = __float2bfloat16(ov[j]);
        lo[j] = __float2bfloat16(ov[j] - __bfloat162float(hi[j]));
    }
    *(uint4*)(ahout + nb + off) = *(uint4*)hi;
    *(uint4*)(alout + nb + off) = *(uint4*)lo;
}

// ============== fused edge attention + epilogue, LAYER 2 ==============
// extra=accea@we, head-mean, +skip2, relu, classifier -> out[N,2].
__global__ __launch_bounds__(256) void fused_attn2_kernel(
    const float* __restrict__ qg, const float* __restrict__ kg,
    const float* __restrict__ vg, const float* __restrict__ pg,
    const int* __restrict__ src, const float* __restrict__ ea,
    const float* __restrict__ we, const float* __restrict__ skip2,
    const float* __restrict__ wc, const float* __restrict__ bc,
    float* __restrict__ out, int M)
{
    __shared__ __align__(16) float W2[8224];
    __shared__ float stage[8][264];
    __shared__ float wcs[64];
    __shared__ float bcs[2];
    int tid = threadIdx.x;
    for (int i = tid; i < 8192; i += 256) {
        int d = i >> 8, col = i & 255;
        W2[(col >> 5) * HS2 + d * 32 + (col & 31)] = we[i];
    }
    if (tid < 64) wcs[tid] = wc[tid];
    if (tid < 2) bcs[tid] = bc[tid];
    __syncthreads();

    int wid = tid >> 5, lane = tid & 31;
    int n = blockIdx.x * 8 + wid;
    if (n >= M) return;
    int h = lane >> 2, chunk = lane & 3, off = lane << 3;
    size_t nb = (size_t)n * 256;

    float4 qa = *(const float4*)(qg + nb + off);
    float4 qb = *(const float4*)(qg + nb + off + 4);
    float4 pa = *(const float4*)(pg + nb + off);
    float4 pb = *(const float4*)(pg + nb + off + 4);

    int beg = g_rowptr[n], end = g_rowptr[n + 1];
    float denom = 0.f;
    float ac0 = 0, ac1 = 0, ac2 = 0, ac3 = 0, ac4 = 0, ac5 = 0, ac6 = 0, ac7 = 0;
    float ae0 = 0, ae1 = 0, ae2 = 0, ae3 = 0, ae4 = 0, ae5 = 0, ae6 = 0, ae7 = 0;

    for (int j = beg; j < end; j++) {
        int e = g_eid[j];
        int s = src[e];
        size_t sbv = (size_t)s * 256;
        size_t eb = (size_t)e * 32 + (chunk << 3);
        float4 ka = *(const float4*)(kg + sbv + off);
        float4 kb = *(const float4*)(kg + sbv + off + 4);
        float4 aa = *(const float4*)(ea + eb);
        float4 ab = *(const float4*)(ea + eb + 4);
        float part = qa.x * ka.x + qa.y * ka.y + qa.z * ka.z + qa.w * ka.w
                   + qb.x * kb.x + qb.y * kb.y + qb.z * kb.z + qb.w * kb.w
                   + pa.x * aa.x + pa.y * aa.y + pa.z * aa.z + pa.w * aa.w
                   + pb.x * ab.x + pb.y * ab.y + pb.z * ab.z + pb.w * ab.w;
        part += __shfl_xor_sync(0xffffffffu, part, 1);
        part += __shfl_xor_sync(0xffffffffu, part, 2);
        float ex = __expf(part * 0.17677669529663687f);

        float4 va = *(const float4*)(vg + sbv + off);
        float4 vb = *(const float4*)(vg + sbv + off + 4);

        denom += ex;
        ac0 = fmaf(ex, va.x, ac0);  ac1 = fmaf(ex, va.y, ac1);
        ac2 = fmaf(ex, va.z, ac2);  ac3 = fmaf(ex, va.w, ac3);
        ac4 = fmaf(ex, vb.x, ac4);  ac5 = fmaf(ex, vb.y, ac5);
        ac6 = fmaf(ex, vb.z, ac6);  ac7 = fmaf(ex, vb.w, ac7);
        ae0 = fmaf(ex, aa.x, ae0);  ae1 = fmaf(ex, aa.y, ae1);
        ae2 = fmaf(ex, aa.z, ae2);  ae3 = fmaf(ex, aa.w, ae3);
        ae4 = fmaf(ex, ab.x, ae4);  ae5 = fmaf(ex, ab.y, ae5);
        ae6 = fmaf(ex, ab.z, ae6);  ae7 = fmaf(ex, ab.w, ae7);
    }

    float inv = 1.f / (denom + 1e-16f);
    float* st = stage[wid];
    int sbase = h * 33 + chunk * 8;
    st[sbase + 0] = ae0 * inv; st[sbase + 1] = ae1 * inv;
    st[sbase + 2] = ae2 * inv; st[sbase + 3] = ae3 * inv;
    st[sbase + 4] = ae4 * inv; st[sbase + 5] = ae5 * inv;
    st[sbase + 6] = ae6 * inv; st[sbase + 7] = ae7 * inv;
    __syncwarp();

    float4 e0 = make_float4(0.f, 0.f, 0.f, 0.f);
    float4 e1 = make_float4(0.f, 0.f, 0.f, 0.f);
    const float* wb = &W2[h * HS2 + chunk * 8];
#pragma unroll
    for (int d = 0; d < 32; d++) {
        float av = st[h * 33 + d];
        float4 w0 = *(const float4*)(wb + d * 32);
        float4 w1 = *(const float4*)(wb + d * 32 + 4);
        e0.x += av * w0.x; e0.y += av * w0.y; e0.z += av * w0.z; e0.w += av * w0.w;
        e1.x += av * w1.x; e1.y += av * w1.y; e1.z += av * w1.z; e1.w += av * w1.w;
    }

    float v[8];
    v[0] = ac0 * inv + e0.x;  v[1] = ac1 * inv + e0.y;
    v[2] = ac2 * inv + e0.z;  v[3] = ac3 * inv + e0.w;
    v[4] = ac4 * inv + e1.x;  v[5] = ac5 * inv + e1.y;
    v[6] = ac6 * inv + e1.z;  v[7] = ac7 * inv + e1.w;

    // head mean: sum over lanes stride-4 (same col-within-head, different head)
#pragma unroll
    for (int j = 0; j < 8; j++) {
        v[j] += __shfl_xor_sync(0xffffffffu, v[j], 4);
        v[j] += __shfl_xor_sync(0xffffffffu, v[j], 8);
        v[j] += __shfl_xor_sync(0xffffffffu, v[j], 16);
    }
    int c0 = chunk * 8;   // col within 32-dim mean
    float4 s2a = *(const float4*)(skip2 + (size_t)n * 32 + c0);
    float4 s2b = *(const float4*)(skip2 + (size_t)n * 32 + c0 + 4);
    float sv[8] = {s2a.x, s2a.y, s2a.z, s2a.w, s2b.x, s2b.y, s2b.z, s2b.w};
    float d0 = 0.f, d1 = 0.f;
#pragma unroll
    for (int j = 0; j < 8; j++) {
        float z = fmaxf(v[j] * 0.125f + sv[j], 0.f);
        d0 += z * wcs[(c0 + j) * 2 + 0];
        d1 += z * wcs[(c0 + j) * 2 + 1];
    }
    d0 += __shfl_xor_sync(0xffffffffu, d0, 1);
    d0 += __shfl_xor_sync(0xffffffffu, d0, 2);
    d1 += __shfl_xor_sync(0xffffffffu, d1, 1);
    d1 += __shfl_xor_sync(0xffffffffu, d1, 2);
    if (lane == 0) {
        out[(size_t)n * 2 + 0] = d0 + bcs[0];
        out[(size_t)n * 2 + 1] = d1 + bcs[1];
    }
}

// ------------------------- skip2: out[N,32] = h[N,256] @ w[256,32] + b -------------------------
__global__ __launch_bounds__(256) void skip2_kernel(
    const float* __restrict__ hin, const float* __restrict__ w,
    const float* __restrict__ b, float* __restrict__ out, int M)
{
    __shared__ float ws[8192];
    __shared__ float xs[8][256];
    int tid = threadIdx.x;
    for (int i = tid; i < 8192; i += 256) ws[i] = w[i];
    int base = blockIdx.x * 8;
    for (int i = 0; i < 8; i++) {
        int n = base + i;
        xs[i][tid] = (n < M) ? hin[(size_t)n * 256 + tid] : 0.f;
    }
    __syncthreads();
    int r = tid >> 5, c = tid & 31;
    float s = b[c];
#pragma unroll 8
    for (int k = 0; k < 256; k++) s += xs[r][k] * ws[k * 32 + c];
    int n = base + r;
    if (n < M) out[(size_t)n * 32 + c] = s;
}

// ------------------------- launcher -------------------------
extern "C" void kernel_launch(void* const* d_in, const int* in_sizes, int n_in,
                              void* d_out, int out_size)
{
    const float* x      = (const float*)d_in[0];
    const int*   eidx   = (const int*)d_in[1];
    const float* eattr  = (const float*)d_in[2];
    const float* wq1    = (const float*)d_in[3];
    const float* bq1    = (const float*)d_in[4];
    const float* wk1    = (const float*)d_in[5];
    const float* bk1    = (const float*)d_in[6];
    const float* wv1    = (const float*)d_in[7];
    const float* bv1    = (const float*)d_in[8];
    const float* we1    = (const float*)d_in[9];
    const float* wskip1 = (const float*)d_in[10];
    const float* bskip1 = (const float*)d_in[11];
    const float* g1     = (const float*)d_in[12];
    const float* b1     = (const float*)d_in[13];
    const float* wq2    = (const float*)d_in[14];
    const float* bq2    = (const float*)d_in[15];
    const float* wk2    = (const float*)d_in[16];
    const float* bk2    = (const float*)d_in[17];
    const float* wv2    = (const float*)d_in[18];
    const float* bv2    = (const float*)d_in[19];
    const float* we2    = (const float*)d_in[20];
    const float* wskip2 = (const float*)d_in[21];
    const float* bskip2 = (const float*)d_in[22];
    const float* wc     = (const float*)d_in[23];
    const float* bc     = (const float*)d_in[24];

    int n = in_sizes[0] / 128;
    int e = in_sizes[1] / 2;
    const int* src = eidx;
    const int* dst = eidx + e;

    float *pq, *pk, *pv, *pp, *ps1, *ph, *ps2;
    __nv_bfloat16 *pah, *pal, *pbh, *pbl;
    cudaGetSymbolAddress((void**)&pq, g_q);
    cudaGetSymbolAddress((void**)&pk, g_k);
    cudaGetSymbolAddress((void**)&pv, g_v);
    cudaGetSymbolAddress((void**)&pp, g_p);
    cudaGetSymbolAddress((void**)&ps1, g_skip1);
    cudaGetSymbolAddress((void**)&ph, g_h);
    cudaGetSymbolAddress((void**)&ps2, g_skip2);
    cudaGetSymbolAddress((void**)&pah, g_ah);
    cudaGetSymbolAddress((void**)&pal, g_al);
    cudaGetSymbolAddress((void**)&pbh, g_bth);
    cudaGetSymbolAddress((void**)&pbl, g_btl);

    cudaFuncSetAttribute(mma_gemm_kernel,
                         cudaFuncAttributeMaxDynamicSharedMemorySize, GEMM_SMEM);

    int nb256 = (n + 255) / 256;
    int eb256 = (e + 255) / 256;
    int nodeBlocks = (n + 7) / 8;
    int mTiles = (n + 127) / 128;

    // Layer-1 projections (mma_gemm stays at launch index 3 for the ncu window)
    conv_a_kernel<<<(n * 128 + 255) / 256, 256>>>(x, n * 128);
    pack_w_kernel<<<(1024 * 128 + 255) / 256, 256>>>(wq1, wk1, wv1, wskip1, 128, 1024);
    zero_deg_kernel<<<nb256, 256>>>(n);
    {
        dim3 grid(4, mTiles);
        mma_gemm_kernel<<<grid, 256, GEMM_SMEM>>>(pah, pal, pbh, pbl,
                                                  bq1, bk1, bv1, bskip1,
                                                  pq, pk, pv, ps1, 128);
    }
    hist_kernel<<<eb256, 256>>>(dst, e);
    scan_kernel<<<1, 1024>>>(n);
    scatter_kernel<<<eb256, 256>>>(dst, e);

    compute_p_kernel<<<nodeBlocks, 256>>>(pq, we1, pp, n);
    fused_attn1_kernel<<<nodeBlocks, 256>>>(pq, pk, pv, pp, src, eattr,
                                            we1, ps1, g1, b1, ph, pah, pal, n);

    // Layer 2 (pah/pal already produced by fused_attn1)
    pack_w_kernel<<<(768 * 256 + 255) / 256, 256>>>(wq2, wk2, wv2, wv2, 256, 768);
    {
        dim3 grid(3, mTiles);
        mma_gemm_kernel<<<grid, 256, GEMM_SMEM>>>(pah, pal, pbh, pbl,
                                                  bq2, bk2, bv2, bv2,
                                                  pq, pk, pv, pv, 256);
    }
    skip2_kernel<<<nodeBlocks, 256>>>(ph, wskip2, bskip2, ps2, n);
    compute_p_kernel<<<nodeBlocks, 256>>>(pq, we2, pp, n);
    fused_attn2_kernel<<<nodeBlocks, 256>>>(pq, pk, pv, pp, src, eattr,
                                            we2, ps2, wc, bc, (float*)d_out, n);
}

// round 13
// speedup vs baseline: 1.1506x; 1.0400x over previous
#include <cuda_runtime.h>
#include <cuda_bf16.h>
#include <math.h>
#include <stdint.h>

#define NMAX 50000
#define NPAD 50048   // 391 * 128
#define EMAX 400000
#define HS2 1028     // per-head stride in W2 smem (conflict-free: 1028 % 32 == 4)

// ------------------------- scratch (static device memory) -------------------------
__device__ float g_q[(size_t)NPAD * 256];
__device__ float g_k[(size_t)NPAD * 256];
__device__ float g_v[(size_t)NPAD * 256];
__device__ float g_p[(size_t)NPAD * 256];
__device__ float g_skip1[(size_t)NPAD * 256];
__device__ float g_h[(size_t)NPAD * 256];
__device__ float g_skip2[(size_t)NPAD * 32];
__device__ __nv_bfloat16 g_ah[(size_t)NPAD * 256];
__device__ __nv_bfloat16 g_al[(size_t)NPAD * 256];
__device__ __nv_bfloat16 g_bth[1024 * 256];
__device__ __nv_bfloat16 g_btl[1024 * 256];
__device__ int g_deg[NMAX];
__device__ int g_rowptr[NMAX + 1];
__device__ int g_cnt[NMAX];
__device__ int g_eid[EMAX];
__device__ int g_esrc[EMAX];

// ------------------------- PTX helpers -------------------------
__device__ __forceinline__ uint32_t smem_u32(const void* p) {
    uint32_t a;
    asm("{ .reg .u64 t; cvta.to.shared.u64 t, %1; cvt.u32.u64 %0, t; }" : "=r"(a) : "l"(p));
    return a;
}
__device__ __forceinline__ void cp16(uint32_t saddr, const void* gaddr) {
    asm volatile("cp.async.cg.shared.global [%0], [%1], 16;" :: "r"(saddr), "l"(gaddr) : "memory");
}
#define CP_COMMIT() asm volatile("cp.async.commit_group;" ::: "memory")
#define CP_WAIT(N)  asm volatile("cp.async.wait_group %0;" :: "n"(N) : "memory")

__device__ __forceinline__ void ldm_x4(uint32_t* r, uint32_t addr) {
    asm volatile("ldmatrix.sync.aligned.m8n8.x4.shared.b16 {%0,%1,%2,%3}, [%4];"
        : "=r"(r[0]), "=r"(r[1]), "=r"(r[2]), "=r"(r[3]) : "r"(addr));
}
__device__ __forceinline__ void mma_bf16(float* c, const uint32_t* a, const uint32_t* b) {
    asm volatile("mma.sync.aligned.m16n8k16.row.col.f32.bf16.bf16.f32 "
        "{%0,%1,%2,%3}, {%4,%5,%6,%7}, {%8,%9}, {%0,%1,%2,%3};"
        : "+f"(c[0]), "+f"(c[1]), "+f"(c[2]), "+f"(c[3])
        : "r"(a[0]), "r"(a[1]), "r"(a[2]), "r"(a[3]), "r"(b[0]), "r"(b[1]));
}

// ------------------------- CSR build -------------------------
__global__ void zero_deg_kernel(int n) {
    int i = blockIdx.x * blockDim.x + threadIdx.x;
    if (i < n) g_deg[i] = 0;
}
__global__ void hist_kernel(const int* __restrict__ dst, int e) {
    int i = blockIdx.x * blockDim.x + threadIdx.x;
    if (i < e) atomicAdd(&g_deg[dst[i]], 1);
}
__global__ void scan_kernel(int n) {
    __shared__ int sums[1024];
    int tid = threadIdx.x;
    int per = (n + 1023) >> 10;
    int beg = tid * per;
    int end = min(beg + per, n);
    int s = 0;
    for (int i = beg; i < end; i++) s += g_deg[i];
    sums[tid] = s;
    __syncthreads();
    for (int o = 1; o < 1024; o <<= 1) {
        int v = (tid >= o) ? sums[tid - o] : 0;
        __syncthreads();
        sums[tid] += v;
        __syncthreads();
    }
    int run = (tid == 0) ? 0 : sums[tid - 1];
    for (int i = beg; i < end; i++) {
        g_rowptr[i] = run;
        g_cnt[i] = run;
        run += g_deg[i];
    }
    if (tid == 1023) g_rowptr[n] = sums[1023];
}
__global__ void scatter_kernel(const int* __restrict__ src, const int* __restrict__ dst, int e) {
    int i = blockIdx.x * blockDim.x + threadIdx.x;
    if (i < e) {
        int pos = atomicAdd(&g_cnt[dst[i]], 1);
        g_eid[pos] = i;
        g_esrc[pos] = src[i];
    }
}

// ------------------------- fp32 -> bf16 hi/lo split (layer-1 input only) ----------
__global__ void conv_a_kernel(const float* __restrict__ a, int total) {
    int i = blockIdx.x * blockDim.x + threadIdx.x;
    if (i < total) {
        float v = a[i];
        __nv_bfloat16 h = __float2bfloat16(v);
        g_ah[i] = h;
        g_al[i] = __float2bfloat16(v - __bfloat162float(h));
    }
}

// pack W segments [K,256] row-major into bt[NC,K] K-major bf16 hi/lo
__global__ void pack_w_kernel(const float* __restrict__ w0, const float* __restrict__ w1,
                              const float* __restrict__ w2, const float* __restrict__ w3,
                              int K, int NC) {
    int idx = blockIdx.x * blockDim.x + threadIdx.x;
    if (idx >= NC * K) return;
    int nc = idx / K, k = idx - nc * K;
    int seg = nc >> 8, c = nc & 255;
    const float* w = (seg == 0) ? w0 : (seg == 1) ? w1 : (seg == 2) ? w2 : w3;
    float v = w[(size_t)k * 256 + c];
    __nv_bfloat16 h = __float2bfloat16(v);
    g_bth[idx] = h;
    g_btl[idx] = __float2bfloat16(v - __bfloat162float(h));
}

// ------------------------- mma.sync bf16-split GEMM, 128x256 CTA tile -------------------------
#define ATILE 10240
#define BTILE 20480
#define STAGEB (2 * ATILE + 2 * BTILE)
#define GEMM_SMEM (2 * STAGEB)

__global__ __launch_bounds__(256, 1) void mma_gemm_kernel(
    const __nv_bfloat16* __restrict__ ah, const __nv_bfloat16* __restrict__ al,
    const __nv_bfloat16* __restrict__ bth, const __nv_bfloat16* __restrict__ btl,
    const float* __restrict__ b0, const float* __restrict__ b1,
    const float* __restrict__ b2, const float* __restrict__ b3,
    float* __restrict__ o0, float* __restrict__ o1,
    float* __restrict__ o2, float* __restrict__ o3,
    int K)
{
    extern __shared__ __align__(128) char smem[];
    uint32_t sb = smem_u32(smem);
    int tid = threadIdx.x;
    int wid = tid >> 5, lane = tid & 31;
    int seg = blockIdx.x;
    int gRow = blockIdx.y * 128;

    const __nv_bfloat16* aH = ah + (size_t)gRow * K;
    const __nv_bfloat16* aL = al + (size_t)gRow * K;
    const __nv_bfloat16* bH = bth + (size_t)seg * 256 * K;
    const __nv_bfloat16* bL = btl + (size_t)seg * 256 * K;

    int chunks = K >> 5;

    auto load_stage = [&](int c, int s) {
        uint32_t base = sb + s * STAGEB;
        int kc = c << 5;
#pragma unroll
        for (int i = 0; i < 2; i++) {
            int cid = tid + i * 256;
            int r = cid >> 2, ch = cid & 3;
            uint32_t sa = base + r * 80 + ch * 16;
            size_t go = (size_t)r * K + kc + ch * 8;
            cp16(sa, aH + go);
            cp16(sa + ATILE, aL + go);
        }
#pragma unroll
        for (int i = 0; i < 4; i++) {
            int cid = tid + i * 256;
            int r = cid >> 2, ch = cid & 3;
            uint32_t sa = base + 2 * ATILE + r * 80 + ch * 16;
            size_t go = (size_t)r * K + kc + ch * 8;
            cp16(sa, bH + go);
            cp16(sa + BTILE, bL + go);
        }
        CP_COMMIT();
    };

    float acc[4][8][4];
#pragma unroll
    for (int a = 0; a < 4; a++)
#pragma unroll
        for (int b = 0; b < 8; b++)
#pragma unroll
            for (int c = 0; c < 4; c++) acc[a][b][c] = 0.f;

    int warp_m = wid >> 2, warp_n = wid & 3;
    int mrow0 = warp_m * 64, ncol0 = warp_n * 64;
    int lrow = lane & 15, lsel = lane >> 4;
    int bnrow = (lane >> 4) * 8 + (lane & 7);
    int bgk = ((lane >> 3) & 1) * 16;

    load_stage(0, 0);

    for (int c = 0; c < chunks; c++) {
        if (c + 1 < chunks) { load_stage(c + 1, (c + 1) & 1); CP_WAIT(1); }
        else CP_WAIT(0);
        __syncthreads();

        uint32_t base = sb + (c & 1) * STAGEB;
#pragma unroll
        for (int kh = 0; kh < 2; kh++) {
            uint32_t a_h[4][4], a_l[4][4];
#pragma unroll
            for (int mt = 0; mt < 4; mt++) {
                uint32_t ra = base + (mrow0 + mt * 16 + lrow) * 80 + kh * 32 + lsel * 16;
                ldm_x4(a_h[mt], ra);
                ldm_x4(a_l[mt], ra + ATILE);
            }
#pragma unroll
            for (int ntp = 0; ntp < 4; ntp++) {
                uint32_t b_h[4], b_l[4];
                uint32_t rb = base + 2 * ATILE + (ncol0 + ntp * 16 + bnrow) * 80 + kh * 32 + bgk;
                ldm_x4(b_h, rb);
                ldm_x4(b_l, rb + BTILE);
#pragma unroll
                for (int mt = 0; mt < 4; mt++) {
                    mma_bf16(acc[mt][2 * ntp],     a_h[mt], b_h);
                    mma_bf16(acc[mt][2 * ntp],     a_h[mt], b_l);
                    mma_bf16(acc[mt][2 * ntp],     a_l[mt], b_h);
                    mma_bf16(acc[mt][2 * ntp + 1], a_h[mt], b_h + 2);
                    mma_bf16(acc[mt][2 * ntp + 1], a_h[mt], b_l + 2);
                    mma_bf16(acc[mt][2 * ntp + 1], a_l[mt], b_h + 2);
                }
            }
        }
        __syncthreads();
    }

    const float* bias = (seg == 0) ? b0 : (seg == 1) ? b1 : (seg == 2) ? b2 : b3;
    float* out = (seg == 0) ? o0 : (seg == 1) ? o1 : (seg == 2) ? o2 : o3;
    int colBase = ncol0 + (lane & 3) * 2;
    int row0 = gRow + mrow0 + (lane >> 2);
#pragma unroll
    for (int mt = 0; mt < 4; mt++) {
        int row = row0 + mt * 16;
#pragma unroll
        for (int nt = 0; nt < 8; nt++) {
            int col = colBase + nt * 8;
            float bv0 = bias[col], bv1 = bias[col + 1];
            float2 v0 = make_float2(acc[mt][nt][0] + bv0, acc[mt][nt][1] + bv1);
            float2 v1 = make_float2(acc[mt][nt][2] + bv0, acc[mt][nt][3] + bv1);
            *(float2*)(out + (size_t)row * 256 + col) = v0;
            *(float2*)(out + (size_t)(row + 8) * 256 + col) = v1;
        }
    }
}

// ------------------------- p[n][h*32+d] = sum_c q[n][h*32+c] * we[d][h*32+c] -------------------------
__global__ __launch_bounds__(256) void compute_p_kernel(
    const float* __restrict__ q, const float* __restrict__ we,
    float* __restrict__ p, int M)
{
    __shared__ float wet[256 * 33];
    __shared__ float qs[8][256];
    int tid = threadIdx.x;
    for (int i = tid; i < 8192; i += 256) {
        int d = i >> 8, col = i & 255;
        wet[col * 33 + d] = we[i];
    }
    int base = blockIdx.x * 8;
    for (int i = 0; i < 8; i++) {
        int n = base + i;
        qs[i][tid] = (n < M) ? q[(size_t)n * 256 + tid] : 0.f;
    }
    __syncthreads();
    int h = tid >> 5, d = tid & 31;
    for (int i = 0; i < 8; i++) {
        int n = base + i;
        if (n >= M) break;
        float s = 0.f;
#pragma unroll
        for (int c = 0; c < 32; c++)
            s += qs[i][h * 32 + c] * wet[(h * 32 + c) * 33 + d];
        p[(size_t)n * 256 + h * 32 + d] = s;
    }
}

// ============== fused edge attention + epilogue, LAYER 1 ==============
// One warp per dst node: direct-exp softmax gather (sequential eid/esrc index
// streams, no dependent src[e] chase), then extra=accea@we, +skip, relu,
// LayerNorm -> h (fp32) + bf16 hi/lo split for layer-2 GEMM.
__global__ __launch_bounds__(256) void fused_attn1_kernel(
    const float* __restrict__ qg, const float* __restrict__ kg,
    const float* __restrict__ vg, const float* __restrict__ pg,
    const float* __restrict__ ea,
    const float* __restrict__ we, const float* __restrict__ skip,
    const float* __restrict__ g, const float* __restrict__ b,
    float* __restrict__ hout, __nv_bfloat16* __restrict__ ahout,
    __nv_bfloat16* __restrict__ alout, int M)
{
    __shared__ __align__(16) float W2[8224];    // [h][d][t] head-stride 1028
    __shared__ float stage[8][264];             // per-warp accea staging (33-padded)
    __shared__ float gsh[256], bsh[256];
    int tid = threadIdx.x;
    for (int i = tid; i < 8192; i += 256) {
        int d = i >> 8, col = i & 255;
        W2[(col >> 5) * HS2 + d * 32 + (col & 31)] = we[i];
    }
    gsh[tid] = g[tid];
    bsh[tid] = b[tid];
    __syncthreads();

    int wid = tid >> 5, lane = tid & 31;
    int n = blockIdx.x * 8 + wid;
    if (n >= M) return;
    int h = lane >> 2, chunk = lane & 3, off = lane << 3;
    size_t nb = (size_t)n * 256;

    float4 qa = *(const float4*)(qg + nb + off);
    float4 qb = *(const float4*)(qg + nb + off + 4);
    float4 pa = *(const float4*)(pg + nb + off);
    float4 pb = *(const float4*)(pg + nb + off + 4);

    int beg = g_rowptr[n], end = g_rowptr[n + 1];
    float denom = 0.f;
    float ac0 = 0, ac1 = 0, ac2 = 0, ac3 = 0, ac4 = 0, ac5 = 0, ac6 = 0, ac7 = 0;
    float ae0 = 0, ae1 = 0, ae2 = 0, ae3 = 0, ae4 = 0, ae5 = 0, ae6 = 0, ae7 = 0;

    for (int j = beg; j < end; j++) {
        int e = g_eid[j];
        int s = g_esrc[j];
        size_t sbv = (size_t)s * 256;
        size_t eb = (size_t)e * 32 + (chunk << 3);
        float4 ka = *(const float4*)(kg + sbv + off);
        float4 kb = *(const float4*)(kg + sbv + off + 4);
        float4 aa = *(const float4*)(ea + eb);
        float4 ab = *(const float4*)(ea + eb + 4);
        float part = qa.x * ka.x + qa.y * ka.y + qa.z * ka.z + qa.w * ka.w
                   + qb.x * kb.x + qb.y * kb.y + qb.z * kb.z + qb.w * kb.w
                   + pa.x * aa.x + pa.y * aa.y + pa.z * aa.z + pa.w * aa.w
                   + pb.x * ab.x + pb.y * ab.y + pb.z * ab.z + pb.w * ab.w;
        part += __shfl_xor_sync(0xffffffffu, part, 1);
        part += __shfl_xor_sync(0xffffffffu, part, 2);
        float ex = __expf(part * 0.17677669529663687f);

        float4 va = *(const float4*)(vg + sbv + off);
        float4 vb = *(const float4*)(vg + sbv + off + 4);

        denom += ex;
        ac0 = fmaf(ex, va.x, ac0);  ac1 = fmaf(ex, va.y, ac1);
        ac2 = fmaf(ex, va.z, ac2);  ac3 = fmaf(ex, va.w, ac3);
        ac4 = fmaf(ex, vb.x, ac4);  ac5 = fmaf(ex, vb.y, ac5);
        ac6 = fmaf(ex, vb.z, ac6);  ac7 = fmaf(ex, vb.w, ac7);
        ae0 = fmaf(ex, aa.x, ae0);  ae1 = fmaf(ex, aa.y, ae1);
        ae2 = fmaf(ex, aa.z, ae2);  ae3 = fmaf(ex, aa.w, ae3);
        ae4 = fmaf(ex, ab.x, ae4);  ae5 = fmaf(ex, ab.y, ae5);
        ae6 = fmaf(ex, ab.z, ae6);  ae7 = fmaf(ex, ab.w, ae7);
    }

    float inv = 1.f / (denom + 1e-16f);
    // stage accea (normalized) at [h*33 + d] (bank-spread across heads)
    float* st = stage[wid];
    int sbase = h * 33 + chunk * 8;
    st[sbase + 0] = ae0 * inv; st[sbase + 1] = ae1 * inv;
    st[sbase + 2] = ae2 * inv; st[sbase + 3] = ae3 * inv;
    st[sbase + 4] = ae4 * inv; st[sbase + 5] = ae5 * inv;
    st[sbase + 6] = ae6 * inv; st[sbase + 7] = ae7 * inv;
    __syncwarp();

    // extra = accea @ we for this lane's 8 cols
    float4 e0 = make_float4(0.f, 0.f, 0.f, 0.f);
    float4 e1 = make_float4(0.f, 0.f, 0.f, 0.f);
    const float* wb = &W2[h * HS2 + chunk * 8];
#pragma unroll
    for (int d = 0; d < 32; d++) {
        float av = st[h * 33 + d];
        float4 w0 = *(const float4*)(wb + d * 32);
        float4 w1 = *(const float4*)(wb + d * 32 + 4);
        e0.x += av * w0.x; e0.y += av * w0.y; e0.z += av * w0.z; e0.w += av * w0.w;
        e1.x += av * w1.x; e1.y += av * w1.y; e1.z += av * w1.z; e1.w += av * w1.w;
    }

    float4 sk0 = *(const float4*)(skip + nb + off);
    float4 sk1 = *(const float4*)(skip + nb + off + 4);
    float v0 = fmaxf(ac0 * inv + e0.x + sk0.x, 0.f);
    float v1 = fmaxf(ac1 * inv + e0.y + sk0.y, 0.f);
    float v2 = fmaxf(ac2 * inv + e0.z + sk0.z, 0.f);
    float v3 = fmaxf(ac3 * inv + e0.w + sk0.w, 0.f);
    float v4 = fmaxf(ac4 * inv + e1.x + sk1.x, 0.f);
    float v5 = fmaxf(ac5 * inv + e1.y + sk1.y, 0.f);
    float v6 = fmaxf(ac6 * inv + e1.z + sk1.z, 0.f);
    float v7 = fmaxf(ac7 * inv + e1.w + sk1.w, 0.f);

    float s1 = v0 + v1 + v2 + v3 + v4 + v5 + v6 + v7;
    float s2 = v0 * v0 + v1 * v1 + v2 * v2 + v3 * v3 + v4 * v4 + v5 * v5 + v6 * v6 + v7 * v7;
#pragma unroll
    for (int o = 16; o > 0; o >>= 1) {
        s1 += __shfl_xor_sync(0xffffffffu, s1, o);
        s2 += __shfl_xor_sync(0xffffffffu, s2, o);
    }
    float mu = s1 * (1.f / 256.f);
    float var = s2 * (1.f / 256.f) - mu * mu;
    float rinv = rsqrtf(var + 1e-5f);

    float o0 = (v0 - mu) * rinv * gsh[off + 0] + bsh[off + 0];
    float o1 = (v1 - mu) * rinv * gsh[off + 1] + bsh[off + 1];
    float o2 = (v2 - mu) * rinv * gsh[off + 2] + bsh[off + 2];
    float o3 = (v3 - mu) * rinv * gsh[off + 3] + bsh[off + 3];
    float o4 = (v4 - mu) * rinv * gsh[off + 4] + bsh[off + 4];
    float o5 = (v5 - mu) * rinv * gsh[off + 5] + bsh[off + 5];
    float o6 = (v6 - mu) * rinv * gsh[off + 6] + bsh[off + 6];
    float o7 = (v7 - mu) * rinv * gsh[off + 7] + bsh[off + 7];

    *(float4*)(hout + nb + off)     = make_float4(o0, o1, o2, o3);
    *(float4*)(hout + nb + off + 4) = make_float4(o4, o5, o6, o7);

    // bf16 hi/lo split for layer-2 GEMM operand
    float ov[8] = {o0, o1, o2, o3, o4, o5, o6, o7};
    __nv_bfloat16 hi[8];
    __nv_bfloat16 lo[8];
#pragma unroll
    for (int j = 0; j < 8; j++) {
        hi[j] = __float2bfloat16(ov[j]);
        lo[j] = __float2bfloat16(ov[j] - __bfloat162float(hi[j]));
    }
    *(uint4*)(ahout + nb + off) = *(uint4*)hi;
    *(uint4*)(alout + nb + off) = *(uint4*)lo;
}

// ============== fused edge attention + epilogue, LAYER 2 ==============
// extra=accea@we, head-mean, +skip2, relu, classifier -> out[N,2].
__global__ __launch_bounds__(256) void fused_attn2_kernel(
    const float* __restrict__ qg, const float* __restrict__ kg,
    const float* __restrict__ vg, const float* __restrict__ pg,
    const float* __restrict__ ea,
    const float* __restrict__ we, const float* __restrict__ skip2,
    const float* __restrict__ wc, const float* __restrict__ bc,
    float* __restrict__ out, int M)
{
    __shared__ __align__(16) float W2[8224];
    __shared__ float stage[8][264];
    __shared__ float wcs[64];
    __shared__ float bcs[2];
    int tid = threadIdx.x;
    for (int i = tid; i < 8192; i += 256) {
        int d = i >> 8, col = i & 255;
        W2[(col >> 5) * HS2 + d * 32 + (col & 31)] = we[i];
    }
    if (tid < 64) wcs[tid] = wc[tid];
    if (tid < 2) bcs[tid] = bc[tid];
    __syncthreads();

    int wid = tid >> 5, lane = tid & 31;
    int n = blockIdx.x * 8 + wid;
    if (n >= M) return;
    int h = lane >> 2, chunk = lane & 3, off = lane << 3;
    size_t nb = (size_t)n * 256;

    float4 qa = *(const float4*)(qg + nb + off);
    float4 qb = *(const float4*)(qg + nb + off + 4);
    float4 pa = *(const float4*)(pg + nb + off);
    float4 pb = *(const float4*)(pg + nb + off + 4);

    int beg = g_rowptr[n], end = g_rowptr[n + 1];
    float denom = 0.f;
    float ac0 = 0, ac1 = 0, ac2 = 0, ac3 = 0, ac4 = 0, ac5 = 0, ac6 = 0, ac7 = 0;
    float ae0 = 0, ae1 = 0, ae2 = 0, ae3 = 0, ae4 = 0, ae5 = 0, ae6 = 0, ae7 = 0;

    for (int j = beg; j < end; j++) {
        int e = g_eid[j];
        int s = g_esrc[j];
        size_t sbv = (size_t)s * 256;
        size_t eb = (size_t)e * 32 + (chunk << 3);
        float4 ka = *(const float4*)(kg + sbv + off);
        float4 kb = *(const float4*)(kg + sbv + off + 4);
        float4 aa = *(const float4*)(ea + eb);
        float4 ab = *(const float4*)(ea + eb + 4);
        float part = qa.x * ka.x + qa.y * ka.y + qa.z * ka.z + qa.w * ka.w
                   + qb.x * kb.x + qb.y * kb.y + qb.z * kb.z + qb.w * kb.w
                   + pa.x * aa.x + pa.y * aa.y + pa.z * aa.z + pa.w * aa.w
                   + pb.x * ab.x + pb.y * ab.y + pb.z * ab.z + pb.w * ab.w;
        part += __shfl_xor_sync(0xffffffffu, part, 1);
        part += __shfl_xor_sync(0xffffffffu, part, 2);
        float ex = __expf(part * 0.17677669529663687f);

        float4 va = *(const float4*)(vg + sbv + off);
        float4 vb = *(const float4*)(vg + sbv + off + 4);

        denom += ex;
        ac0 = fmaf(ex, va.x, ac0);  ac1 = fmaf(ex, va.y, ac1);
        ac2 = fmaf(ex, va.z, ac2);  ac3 = fmaf(ex, va.w, ac3);
        ac4 = fmaf(ex, vb.x, ac4);  ac5 = fmaf(ex, vb.y, ac5);
        ac6 = fmaf(ex, vb.z, ac6);  ac7 = fmaf(ex, vb.w, ac7);
        ae0 = fmaf(ex, aa.x, ae0);  ae1 = fmaf(ex, aa.y, ae1);
        ae2 = fmaf(ex, aa.z, ae2);  ae3 = fmaf(ex, aa.w, ae3);
        ae4 = fmaf(ex, ab.x, ae4);  ae5 = fmaf(ex, ab.y, ae5);
        ae6 = fmaf(ex, ab.z, ae6);  ae7 = fmaf(ex, ab.w, ae7);
    }

    float inv = 1.f / (denom + 1e-16f);
    float* st = stage[wid];
    int sbase = h * 33 + chunk * 8;
    st[sbase + 0] = ae0 * inv; st[sbase + 1] = ae1 * inv;
    st[sbase + 2] = ae2 * inv; st[sbase + 3] = ae3 * inv;
    st[sbase + 4] = ae4 * inv; st[sbase + 5] = ae5 * inv;
    st[sbase + 6] = ae6 * inv; st[sbase + 7] = ae7 * inv;
    __syncwarp();

    float4 e0 = make_float4(0.f, 0.f, 0.f, 0.f);
    float4 e1 = make_float4(0.f, 0.f, 0.f, 0.f);
    const float* wb = &W2[h * HS2 + chunk * 8];
#pragma unroll
    for (int d = 0; d < 32; d++) {
        float av = st[h * 33 + d];
        float4 w0 = *(const float4*)(wb + d * 32);
        float4 w1 = *(const float4*)(wb + d * 32 + 4);
        e0.x += av * w0.x; e0.y += av * w0.y; e0.z += av * w0.z; e0.w += av * w0.w;
        e1.x += av * w1.x; e1.y += av * w1.y; e1.z += av * w1.z; e1.w += av * w1.w;
    }

    float v[8];
    v[0] = ac0 * inv + e0.x;  v[1] = ac1 * inv + e0.y;
    v[2] = ac2 * inv + e0.z;  v[3] = ac3 * inv + e0.w;
    v[4] = ac4 * inv + e1.x;  v[5] = ac5 * inv + e1.y;
    v[6] = ac6 * inv + e1.z;  v[7] = ac7 * inv + e1.w;

    // head mean: sum over lanes stride-4 (same col-within-head, different head)
#pragma unroll
    for (int j = 0; j < 8; j++) {
        v[j] += __shfl_xor_sync(0xffffffffu, v[j], 4);
        v[j] += __shfl_xor_sync(0xffffffffu, v[j], 8);
        v[j] += __shfl_xor_sync(0xffffffffu, v[j], 16);
    }
    int c0 = chunk * 8;   // col within 32-dim mean
    float4 s2a = *(const float4*)(skip2 + (size_t)n * 32 + c0);
    float4 s2b = *(const float4*)(skip2 + (size_t)n * 32 + c0 + 4);
    float sv[8] = {s2a.x, s2a.y, s2a.z, s2a.w, s2b.x, s2b.y, s2b.z, s2b.w};
    float d0 = 0.f, d1 = 0.f;
#pragma unroll
    for (int j = 0; j < 8; j++) {
        float z = fmaxf(v[j] * 0.125f + sv[j], 0.f);
        d0 += z * wcs[(c0 + j) * 2 + 0];
        d1 += z * wcs[(c0 + j) * 2 + 1];
    }
    d0 += __shfl_xor_sync(0xffffffffu, d0, 1);
    d0 += __shfl_xor_sync(0xffffffffu, d0, 2);
    d1 += __shfl_xor_sync(0xffffffffu, d1, 1);
    d1 += __shfl_xor_sync(0xffffffffu, d1, 2);
    if (lane == 0) {
        out[(size_t)n * 2 + 0] = d0 + bcs[0];
        out[(size_t)n * 2 + 1] = d1 + bcs[1];
    }
}

// ------------------------- skip2: out[N,32] = h[N,256] @ w[256,32] + b -------------------------
__global__ __launch_bounds__(256) void skip2_kernel(
    const float* __restrict__ hin, const float* __restrict__ w,
    const float* __restrict__ b, float* __restrict__ out, int M)
{
    __shared__ float ws[8192];
    __shared__ float xs[8][256];
    int tid = threadIdx.x;
    for (int i = tid; i < 8192; i += 256) ws[i] = w[i];
    int base = blockIdx.x * 8;
    for (int i = 0; i < 8; i++) {
        int n = base + i;
        xs[i][tid] = (n < M) ? hin[(size_t)n * 256 + tid] : 0.f;
    }
    __syncthreads();
    int r = tid >> 5, c = tid & 31;
    float s = b[c];
#pragma unroll 8
    for (int k = 0; k < 256; k++) s += xs[r][k] * ws[k * 32 + c];
    int n = base + r;
    if (n < M) out[(size_t)n * 32 + c] = s;
}

// ------------------------- launcher -------------------------
extern "C" void kernel_launch(void* const* d_in, const int* in_sizes, int n_in,
                              void* d_out, int out_size)
{
    const float* x      = (const float*)d_in[0];
    const int*   eidx   = (const int*)d_in[1];
    const float* eattr  = (const float*)d_in[2];
    const float* wq1    = (const float*)d_in[3];
    const float* bq1    = (const float*)d_in[4];
    const float* wk1    = (const float*)d_in[5];
    const float* bk1    = (const float*)d_in[6];
    const float* wv1    = (const float*)d_in[7];
    const float* bv1    = (const float*)d_in[8];
    const float* we1    = (const float*)d_in[9];
    const float* wskip1 = (const float*)d_in[10];
    const float* bskip1 = (const float*)d_in[11];
    const float* g1     = (const float*)d_in[12];
    const float* b1     = (const float*)d_in[13];
    const float* wq2    = (const float*)d_in[14];
    const float* bq2    = (const float*)d_in[15];
    const float* wk2    = (const float*)d_in[16];
    const float* bk2    = (const float*)d_in[17];
    const float* wv2    = (const float*)d_in[18];
    const float* bv2    = (const float*)d_in[19];
    const float* we2    = (const float*)d_in[20];
    const float* wskip2 = (const float*)d_in[21];
    const float* bskip2 = (const float*)d_in[22];
    const float* wc     = (const float*)d_in[23];
    const float* bc     = (const float*)d_in[24];

    int n = in_sizes[0] / 128;
    int e = in_sizes[1] / 2;
    const int* src = eidx;
    const int* dst = eidx + e;

    float *pq, *pk, *pv, *pp, *ps1, *ph, *ps2;
    __nv_bfloat16 *pah, *pal, *pbh, *pbl;
    cudaGetSymbolAddress((void**)&pq, g_q);
    cudaGetSymbolAddress((void**)&pk, g_k);
    cudaGetSymbolAddress((void**)&pv, g_v);
    cudaGetSymbolAddress((void**)&pp, g_p);
    cudaGetSymbolAddress((void**)&ps1, g_skip1);
    cudaGetSymbolAddress((void**)&ph, g_h);
    cudaGetSymbolAddress((void**)&ps2, g_skip2);
    cudaGetSymbolAddress((void**)&pah, g_ah);
    cudaGetSymbolAddress((void**)&pal, g_al);
    cudaGetSymbolAddress((void**)&pbh, g_bth);
    cudaGetSymbolAddress((void**)&pbl, g_btl);

    cudaFuncSetAttribute(mma_gemm_kernel,
                         cudaFuncAttributeMaxDynamicSharedMemorySize, GEMM_SMEM);

    int nb256 = (n + 255) / 256;
    int eb256 = (e + 255) / 256;
    int nodeBlocks = (n + 7) / 8;
    int mTiles = (n + 127) / 128;

    // Layer-1 projections (mma_gemm stays at launch index 3 for the ncu window)
    conv_a_kernel<<<(n * 128 + 255) / 256, 256>>>(x, n * 128);
    pack_w_kernel<<<(1024 * 128 + 255) / 256, 256>>>(wq1, wk1, wv1, wskip1, 128, 1024);
    zero_deg_kernel<<<nb256, 256>>>(n);
    {
        dim3 grid(4, mTiles);
        mma_gemm_kernel<<<grid, 256, GEMM_SMEM>>>(pah, pal, pbh, pbl,
                                                  bq1, bk1, bv1, bskip1,
                                                  pq, pk, pv, ps1, 128);
    }
    hist_kernel<<<eb256, 256>>>(dst, e);
    scan_kernel<<<1, 1024>>>(n);
    scatter_kernel<<<eb256, 256>>>(src, dst, e);

    compute_p_kernel<<<nodeBlocks, 256>>>(pq, we1, pp, n);
    fused_attn1_kernel<<<nodeBlocks, 256>>>(pq, pk, pv, pp, eattr,
                                            we1, ps1, g1, b1, ph, pah, pal, n);

    // Layer 2 (pah/pal already produced by fused_attn1)
    pack_w_kernel<<<(768 * 256 + 255) / 256, 256>>>(wq2, wk2, wv2, wv2, 256, 768);
    {
        dim3 grid(3, mTiles);
        mma_gemm_kernel<<<grid, 256, GEMM_SMEM>>>(pah, pal, pbh, pbl,
                                                  bq2, bk2, bv2, bv2,
                                                  pq, pk, pv, pv, 256);
    }
    skip2_kernel<<<nodeBlocks, 256>>>(ph, wskip2, bskip2, ps2, n);
    compute_p_kernel<<<nodeBlocks, 256>>>(pq, we2, pp, n);
    fused_attn2_kernel<<<nodeBlocks, 256>>>(pq, pk, pv, pp, eattr,
                                            we2, ps2, wc, bc, (float*)d_out, n);
}

// round 14
// speedup vs baseline: 1.2024x; 1.0450x over previous
#include <cuda_runtime.h>
#include <cuda_bf16.h>
#include <math.h>
#include <stdint.h>

#define NMAX 50000
#define NPAD 50048   // 391 * 128
#define EMAX 400000
#define HS2 1028     // per-head stride in W2 smem (conflict-free: 1028 % 32 == 4)

// ------------------------- scratch (static device memory) -------------------------
__device__ float g_q[(size_t)NPAD * 256];
__device__ float g_k[(size_t)NPAD * 256];
__device__ float g_v[(size_t)NPAD * 256];
__device__ float g_p[(size_t)NPAD * 256];
__device__ float g_skip1[(size_t)NPAD * 256];
__device__ float g_h[(size_t)NPAD * 256];
__device__ float g_skip2[(size_t)NPAD * 32];
__device__ float g_eacsr[(size_t)EMAX * 32];
__device__ __nv_bfloat16 g_ah[(size_t)NPAD * 256];
__device__ __nv_bfloat16 g_al[(size_t)NPAD * 256];
__device__ __nv_bfloat16 g_bth[1024 * 256];
__device__ __nv_bfloat16 g_btl[1024 * 256];
__device__ int g_deg[NMAX];
__device__ int g_rowptr[NMAX + 1];
__device__ int g_cnt[NMAX];
__device__ int g_eid[EMAX];
__device__ int g_esrc[EMAX];

// ------------------------- PTX helpers -------------------------
__device__ __forceinline__ uint32_t smem_u32(const void* p) {
    uint32_t a;
    asm("{ .reg .u64 t; cvta.to.shared.u64 t, %1; cvt.u32.u64 %0, t; }" : "=r"(a) : "l"(p));
    return a;
}
__device__ __forceinline__ void cp16(uint32_t saddr, const void* gaddr) {
    asm volatile("cp.async.cg.shared.global [%0], [%1], 16;" :: "r"(saddr), "l"(gaddr) : "memory");
}
#define CP_COMMIT() asm volatile("cp.async.commit_group;" ::: "memory")
#define CP_WAIT(N)  asm volatile("cp.async.wait_group %0;" :: "n"(N) : "memory")

__device__ __forceinline__ void ldm_x4(uint32_t* r, uint32_t addr) {
    asm volatile("ldmatrix.sync.aligned.m8n8.x4.shared.b16 {%0,%1,%2,%3}, [%4];"
        : "=r"(r[0]), "=r"(r[1]), "=r"(r[2]), "=r"(r[3]) : "r"(addr));
}
__device__ __forceinline__ void mma_bf16(float* c, const uint32_t* a, const uint32_t* b) {
    asm volatile("mma.sync.aligned.m16n8k16.row.col.f32.bf16.bf16.f32 "
        "{%0,%1,%2,%3}, {%4,%5,%6,%7}, {%8,%9}, {%0,%1,%2,%3};"
        : "+f"(c[0]), "+f"(c[1]), "+f"(c[2]), "+f"(c[3])
        : "r"(a[0]), "r"(a[1]), "r"(a[2]), "r"(a[3]), "r"(b[0]), "r"(b[1]));
}

// ------------------------- CSR build -------------------------
__global__ void zero_deg_kernel(int n) {
    int i = blockIdx.x * blockDim.x + threadIdx.x;
    if (i < n) g_deg[i] = 0;
}
__global__ void hist_kernel(const int* __restrict__ dst, int e) {
    int i = blockIdx.x * blockDim.x + threadIdx.x;
    if (i < e) atomicAdd(&g_deg[dst[i]], 1);
}
__global__ void scan_kernel(int n) {
    __shared__ int sums[1024];
    int tid = threadIdx.x;
    int per = (n + 1023) >> 10;
    int beg = tid * per;
    int end = min(beg + per, n);
    int s = 0;
    for (int i = beg; i < end; i++) s += g_deg[i];
    sums[tid] = s;
    __syncthreads();
    for (int o = 1; o < 1024; o <<= 1) {
        int v = (tid >= o) ? sums[tid - o] : 0;
        __syncthreads();
        sums[tid] += v;
        __syncthreads();
    }
    int run = (tid == 0) ? 0 : sums[tid - 1];
    for (int i = beg; i < end; i++) {
        g_rowptr[i] = run;
        g_cnt[i] = run;
        run += g_deg[i];
    }
    if (tid == 1023) g_rowptr[n] = sums[1023];
}
__global__ void scatter_kernel(const int* __restrict__ src, const int* __restrict__ dst, int e) {
    int i = blockIdx.x * blockDim.x + threadIdx.x;
    if (i < e) {
        int pos = atomicAdd(&g_cnt[dst[i]], 1);
        g_eid[pos] = i;
        g_esrc[pos] = src[i];
    }
}
// reorder edge_attr into CSR order: 8 lanes per slot, random 128B reads, sequential writes
__global__ void reorder_ea_kernel(const float* __restrict__ ea, int e) {
    int gtid = blockIdx.x * blockDim.x + threadIdx.x;
    int j = gtid >> 3, part = gtid & 7;
    if (j < e) {
        int src_e = g_eid[j];
        *(float4*)(g_eacsr + (size_t)j * 32 + part * 4) =
            *(const float4*)(ea + (size_t)src_e * 32 + part * 4);
    }
}

// ------------------------- fp32 -> bf16 hi/lo split (layer-1 input only) ----------
__global__ void conv_a_kernel(const float* __restrict__ a, int total) {
    int i = blockIdx.x * blockDim.x + threadIdx.x;
    if (i < total) {
        float v = a[i];
        __nv_bfloat16 h = __float2bfloat16(v);
        g_ah[i] = h;
        g_al[i] = __float2bfloat16(v - __bfloat162float(h));
    }
}

// pack W segments [K,256] row-major into bt[NC,K] K-major bf16 hi/lo
__global__ void pack_w_kernel(const float* __restrict__ w0, const float* __restrict__ w1,
                              const float* __restrict__ w2, const float* __restrict__ w3,
                              int K, int NC) {
    int idx = blockIdx.x * blockDim.x + threadIdx.x;
    if (idx >= NC * K) return;
    int nc = idx / K, k = idx - nc * K;
    int seg = nc >> 8, c = nc & 255;
    const float* w = (seg == 0) ? w0 : (seg == 1) ? w1 : (seg == 2) ? w2 : w3;
    float v = w[(size_t)k * 256 + c];
    __nv_bfloat16 h = __float2bfloat16(v);
    g_bth[idx] = h;
    g_btl[idx] = __float2bfloat16(v - __bfloat162float(h));
}

// ------------------------- mma.sync bf16-split GEMM, 128x256 CTA tile -------------------------
#define ATILE 10240
#define BTILE 20480
#define STAGEB (2 * ATILE + 2 * BTILE)
#define GEMM_SMEM (2 * STAGEB)

__global__ __launch_bounds__(256, 1) void mma_gemm_kernel(
    const __nv_bfloat16* __restrict__ ah, const __nv_bfloat16* __restrict__ al,
    const __nv_bfloat16* __restrict__ bth, const __nv_bfloat16* __restrict__ btl,
    const float* __restrict__ b0, const float* __restrict__ b1,
    const float* __restrict__ b2, const float* __restrict__ b3,
    float* __restrict__ o0, float* __restrict__ o1,
    float* __restrict__ o2, float* __restrict__ o3,
    int K)
{
    extern __shared__ __align__(128) char smem[];
    uint32_t sb = smem_u32(smem);
    int tid = threadIdx.x;
    int wid = tid >> 5, lane = tid & 31;
    int seg = blockIdx.x;
    int gRow = blockIdx.y * 128;

    const __nv_bfloat16* aH = ah + (size_t)gRow * K;
    const __nv_bfloat16* aL = al + (size_t)gRow * K;
    const __nv_bfloat16* bH = bth + (size_t)seg * 256 * K;
    const __nv_bfloat16* bL = btl + (size_t)seg * 256 * K;

    int chunks = K >> 5;

    auto load_stage = [&](int c, int s) {
        uint32_t base = sb + s * STAGEB;
        int kc = c << 5;
#pragma unroll
        for (int i = 0; i < 2; i++) {
            int cid = tid + i * 256;
            int r = cid >> 2, ch = cid & 3;
            uint32_t sa = base + r * 80 + ch * 16;
            size_t go = (size_t)r * K + kc + ch * 8;
            cp16(sa, aH + go);
            cp16(sa + ATILE, aL + go);
        }
#pragma unroll
        for (int i = 0; i < 4; i++) {
            int cid = tid + i * 256;
            int r = cid >> 2, ch = cid & 3;
            uint32_t sa = base + 2 * ATILE + r * 80 + ch * 16;
            size_t go = (size_t)r * K + kc + ch * 8;
            cp16(sa, bH + go);
            cp16(sa + BTILE, bL + go);
        }
        CP_COMMIT();
    };

    float acc[4][8][4];
#pragma unroll
    for (int a = 0; a < 4; a++)
#pragma unroll
        for (int b = 0; b < 8; b++)
#pragma unroll
            for (int c = 0; c < 4; c++) acc[a][b][c] = 0.f;

    int warp_m = wid >> 2, warp_n = wid & 3;
    int mrow0 = warp_m * 64, ncol0 = warp_n * 64;
    int lrow = lane & 15, lsel = lane >> 4;
    int bnrow = (lane >> 4) * 8 + (lane & 7);
    int bgk = ((lane >> 3) & 1) * 16;

    load_stage(0, 0);

    for (int c = 0; c < chunks; c++) {
        if (c + 1 < chunks) { load_stage(c + 1, (c + 1) & 1); CP_WAIT(1); }
        else CP_WAIT(0);
        __syncthreads();

        uint32_t base = sb + (c & 1) * STAGEB;
#pragma unroll
        for (int kh = 0; kh < 2; kh++) {
            uint32_t a_h[4][4], a_l[4][4];
#pragma unroll
            for (int mt = 0; mt < 4; mt++) {
                uint32_t ra = base + (mrow0 + mt * 16 + lrow) * 80 + kh * 32 + lsel * 16;
                ldm_x4(a_h[mt], ra);
                ldm_x4(a_l[mt], ra + ATILE);
            }
#pragma unroll
            for (int ntp = 0; ntp < 4; ntp++) {
                uint32_t b_h[4], b_l[4];
                uint32_t rb = base + 2 * ATILE + (ncol0 + ntp * 16 + bnrow) * 80 + kh * 32 + bgk;
                ldm_x4(b_h, rb);
                ldm_x4(b_l, rb + BTILE);
#pragma unroll
                for (int mt = 0; mt < 4; mt++) {
                    mma_bf16(acc[mt][2 * ntp],     a_h[mt], b_h);
                    mma_bf16(acc[mt][2 * ntp],     a_h[mt], b_l);
                    mma_bf16(acc[mt][2 * ntp],     a_l[mt], b_h);
                    mma_bf16(acc[mt][2 * ntp + 1], a_h[mt], b_h + 2);
                    mma_bf16(acc[mt][2 * ntp + 1], a_h[mt], b_l + 2);
                    mma_bf16(acc[mt][2 * ntp + 1], a_l[mt], b_h + 2);
                }
            }
        }
        __syncthreads();
    }

    const float* bias = (seg == 0) ? b0 : (seg == 1) ? b1 : (seg == 2) ? b2 : b3;
    float* out = (seg == 0) ? o0 : (seg == 1) ? o1 : (seg == 2) ? o2 : o3;
    int colBase = ncol0 + (lane & 3) * 2;
    int row0 = gRow + mrow0 + (lane >> 2);
#pragma unroll
    for (int mt = 0; mt < 4; mt++) {
        int row = row0 + mt * 16;
#pragma unroll
        for (int nt = 0; nt < 8; nt++) {
            int col = colBase + nt * 8;
            float bv0 = bias[col], bv1 = bias[col + 1];
            float2 v0 = make_float2(acc[mt][nt][0] + bv0, acc[mt][nt][1] + bv1);
            float2 v1 = make_float2(acc[mt][nt][2] + bv0, acc[mt][nt][3] + bv1);
            *(float2*)(out + (size_t)row * 256 + col) = v0;
            *(float2*)(out + (size_t)(row + 8) * 256 + col) = v1;
        }
    }
}

// ------------------------- p[n][h*32+d] = sum_c q[n][h*32+c] * we[d][h*32+c] -------------------------
__global__ __launch_bounds__(256) void compute_p_kernel(
    const float* __restrict__ q, const float* __restrict__ we,
    float* __restrict__ p, int M)
{
    __shared__ float wet[256 * 33];
    __shared__ float qs[8][256];
    int tid = threadIdx.x;
    for (int i = tid; i < 8192; i += 256) {
        int d = i >> 8, col = i & 255;
        wet[col * 33 + d] = we[i];
    }
    int base = blockIdx.x * 8;
    for (int i = 0; i < 8; i++) {
        int n = base + i;
        qs[i][tid] = (n < M) ? q[(size_t)n * 256 + tid] : 0.f;
    }
    __syncthreads();
    int h = tid >> 5, d = tid & 31;
    for (int i = 0; i < 8; i++) {
        int n = base + i;
        if (n >= M) break;
        float s = 0.f;
#pragma unroll
        for (int c = 0; c < 32; c++)
            s += qs[i][h * 32 + c] * wet[(h * 32 + c) * 33 + d];
        p[(size_t)n * 256 + h * 32 + d] = s;
    }
}

// ============== fused edge attention + epilogue, LAYER 1 ==============
// One warp per dst node: direct-exp softmax gather. Indices (esrc) and edge
// attrs (eacsr) are both CSR-ordered -> fully sequential streams; only the
// k/v gather is random. Then extra=accea@we, +skip, relu, LayerNorm -> h
// (fp32) + bf16 hi/lo split for layer-2 GEMM.
__global__ __launch_bounds__(256) void fused_attn1_kernel(
    const float* __restrict__ qg, const float* __restrict__ kg,
    const float* __restrict__ vg, const float* __restrict__ pg,
    const float* __restrict__ we, const float* __restrict__ skip,
    const float* __restrict__ g, const float* __restrict__ b,
    float* __restrict__ hout, __nv_bfloat16* __restrict__ ahout,
    __nv_bfloat16* __restrict__ alout, int M)
{
    __shared__ __align__(16) float W2[8224];    // [h][d][t] head-stride 1028
    __shared__ float stage[8][264];             // per-warp accea staging (33-padded)
    __shared__ float gsh[256], bsh[256];
    int tid = threadIdx.x;
    for (int i = tid; i < 8192; i += 256) {
        int d = i >> 8, col = i & 255;
        W2[(col >> 5) * HS2 + d * 32 + (col & 31)] = we[i];
    }
    gsh[tid] = g[tid];
    bsh[tid] = b[tid];
    __syncthreads();

    int wid = tid >> 5, lane = tid & 31;
    int n = blockIdx.x * 8 + wid;
    if (n >= M) return;
    int h = lane >> 2, chunk = lane & 3, off = lane << 3;
    size_t nb = (size_t)n * 256;

    float4 qa = *(const float4*)(qg + nb + off);
    float4 qb = *(const float4*)(qg + nb + off + 4);
    float4 pa = *(const float4*)(pg + nb + off);
    float4 pb = *(const float4*)(pg + nb + off + 4);

    int beg = g_rowptr[n], end = g_rowptr[n + 1];
    float denom = 0.f;
    float ac0 = 0, ac1 = 0, ac2 = 0, ac3 = 0, ac4 = 0, ac5 = 0, ac6 = 0, ac7 = 0;
    float ae0 = 0, ae1 = 0, ae2 = 0, ae3 = 0, ae4 = 0, ae5 = 0, ae6 = 0, ae7 = 0;

    for (int j = beg; j < end; j++) {
        int s = g_esrc[j];
        size_t sbv = (size_t)s * 256;
        const float* eap = g_eacsr + (size_t)j * 32 + (chunk << 3);
        float4 ka = *(const float4*)(kg + sbv + off);
        float4 kb = *(const float4*)(kg + sbv + off + 4);
        float4 aa = *(const float4*)(eap);
        float4 ab = *(const float4*)(eap + 4);
        float part = qa.x * ka.x + qa.y * ka.y + qa.z * ka.z + qa.w * ka.w
                   + qb.x * kb.x + qb.y * kb.y + qb.z * kb.z + qb.w * kb.w
                   + pa.x * aa.x + pa.y * aa.y + pa.z * aa.z + pa.w * aa.w
                   + pb.x * ab.x + pb.y * ab.y + pb.z * ab.z + pb.w * ab.w;
        part += __shfl_xor_sync(0xffffffffu, part, 1);
        part += __shfl_xor_sync(0xffffffffu, part, 2);
        float ex = __expf(part * 0.17677669529663687f);

        float4 va = *(const float4*)(vg + sbv + off);
        float4 vb = *(const float4*)(vg + sbv + off + 4);

        denom += ex;
        ac0 = fmaf(ex, va.x, ac0);  ac1 = fmaf(ex, va.y, ac1);
        ac2 = fmaf(ex, va.z, ac2);  ac3 = fmaf(ex, va.w, ac3);
        ac4 = fmaf(ex, vb.x, ac4);  ac5 = fmaf(ex, vb.y, ac5);
        ac6 = fmaf(ex, vb.z, ac6);  ac7 = fmaf(ex, vb.w, ac7);
        ae0 = fmaf(ex, aa.x, ae0);  ae1 = fmaf(ex, aa.y, ae1);
        ae2 = fmaf(ex, aa.z, ae2);  ae3 = fmaf(ex, aa.w, ae3);
        ae4 = fmaf(ex, ab.x, ae4);  ae5 = fmaf(ex, ab.y, ae5);
        ae6 = fmaf(ex, ab.z, ae6);  ae7 = fmaf(ex, ab.w, ae7);
    }

    float inv = 1.f / (denom + 1e-16f);
    // stage accea (normalized) at [h*33 + d] (bank-spread across heads)
    float* st = stage[wid];
    int sbase = h * 33 + chunk * 8;
    st[sbase + 0] = ae0 * inv; st[sbase + 1] = ae1 * inv;
    st[sbase + 2] = ae2 * inv; st[sbase + 3] = ae3 * inv;
    st[sbase + 4] = ae4 * inv; st[sbase + 5] = ae5 * inv;
    st[sbase + 6] = ae6 * inv; st[sbase + 7] = ae7 * inv;
    __syncwarp();

    // extra = accea @ we for this lane's 8 cols
    float4 e0 = make_float4(0.f, 0.f, 0.f, 0.f);
    float4 e1 = make_float4(0.f, 0.f, 0.f, 0.f);
    const float* wb = &W2[h * HS2 + chunk * 8];
#pragma unroll
    for (int d = 0; d < 32; d++) {
        float av = st[h * 33 + d];
        float4 w0 = *(const float4*)(wb + d * 32);
        float4 w1 = *(const float4*)(wb + d * 32 + 4);
        e0.x += av * w0.x; e0.y += av * w0.y; e0.z += av * w0.z; e0.w += av * w0.w;
        e1.x += av * w1.x; e1.y += av * w1.y; e1.z += av * w1.z; e1.w += av * w1.w;
    }

    float4 sk0 = *(const float4*)(skip + nb + off);
    float4 sk1 = *(const float4*)(skip + nb + off + 4);
    float v0 = fmaxf(ac0 * inv + e0.x + sk0.x, 0.f);
    float v1 = fmaxf(ac1 * inv + e0.y + sk0.y, 0.f);
    float v2 = fmaxf(ac2 * inv + e0.z + sk0.z, 0.f);
    float v3 = fmaxf(ac3 * inv + e0.w + sk0.w, 0.f);
    float v4 = fmaxf(ac4 * inv + e1.x + sk1.x, 0.f);
    float v5 = fmaxf(ac5 * inv + e1.y + sk1.y, 0.f);
    float v6 = fmaxf(ac6 * inv + e1.z + sk1.z, 0.f);
    float v7 = fmaxf(ac7 * inv + e1.w + sk1.w, 0.f);

    float s1 = v0 + v1 + v2 + v3 + v4 + v5 + v6 + v7;
    float s2 = v0 * v0 + v1 * v1 + v2 * v2 + v3 * v3 + v4 * v4 + v5 * v5 + v6 * v6 + v7 * v7;
#pragma unroll
    for (int o = 16; o > 0; o >>= 1) {
        s1 += __shfl_xor_sync(0xffffffffu, s1, o);
        s2 += __shfl_xor_sync(0xffffffffu, s2, o);
    }
    float mu = s1 * (1.f / 256.f);
    float var = s2 * (1.f / 256.f) - mu * mu;
    float rinv = rsqrtf(var + 1e-5f);

    float o0 = (v0 - mu) * rinv * gsh[off + 0] + bsh[off + 0];
    float o1 = (v1 - mu) * rinv * gsh[off + 1] + bsh[off + 1];
    float o2 = (v2 - mu) * rinv * gsh[off + 2] + bsh[off + 2];
    float o3 = (v3 - mu) * rinv * gsh[off + 3] + bsh[off + 3];
    float o4 = (v4 - mu) * rinv * gsh[off + 4] + bsh[off + 4];
    float o5 = (v5 - mu) * rinv * gsh[off + 5] + bsh[off + 5];
    float o6 = (v6 - mu) * rinv * gsh[off + 6] + bsh[off + 6];
    float o7 = (v7 - mu) * rinv * gsh[off + 7] + bsh[off + 7];

    *(float4*)(hout + nb + off)     = make_float4(o0, o1, o2, o3);
    *(float4*)(hout + nb + off + 4) = make_float4(o4, o5, o6, o7);

    // bf16 hi/lo split for layer-2 GEMM operand
    float ov[8] = {o0, o1, o2, o3, o4, o5, o6, o7};
    __nv_bfloat16 hi[8];
    __nv_bfloat16 lo[8];
#pragma unroll
    for (int j = 0; j < 8; j++) {
        hi[j] = __float2bfloat16(ov[j]);
        lo[j] = __float2bfloat16(ov[j] - __bfloat162float(hi[j]));
    }
    *(uint4*)(ahout + nb + off) = *(uint4*)hi;
    *(uint4*)(alout + nb + off) = *(uint4*)lo;
}

// ============== fused edge attention + epilogue, LAYER 2 ==============
// extra=accea@we, head-mean, +skip2, relu, classifier -> out[N,2].
__global__ __launch_bounds__(256) void fused_attn2_kernel(
    const float* __restrict__ qg, const float* __restrict__ kg,
    const float* __restrict__ vg, const float* __restrict__ pg,
    const float* __restrict__ we, const float* __restrict__ skip2,
    const float* __restrict__ wc, const float* __restrict__ bc,
    float* __restrict__ out, int M)
{
    __shared__ __align__(16) float W2[8224];
    __shared__ float stage[8][264];
    __shared__ float wcs[64];
    __shared__ float bcs[2];
    int tid = threadIdx.x;
    for (int i = tid; i < 8192; i += 256) {
        int d = i >> 8, col = i & 255;
        W2[(col >> 5) * HS2 + d * 32 + (col & 31)] = we[i];
    }
    if (tid < 64) wcs[tid] = wc[tid];
    if (tid < 2) bcs[tid] = bc[tid];
    __syncthreads();

    int wid = tid >> 5, lane = tid & 31;
    int n = blockIdx.x * 8 + wid;
    if (n >= M) return;
    int h = lane >> 2, chunk = lane & 3, off = lane << 3;
    size_t nb = (size_t)n * 256;

    float4 qa = *(const float4*)(qg + nb + off);
    float4 qb = *(const float4*)(qg + nb + off + 4);
    float4 pa = *(const float4*)(pg + nb + off);
    float4 pb = *(const float4*)(pg + nb + off + 4);

    int beg = g_rowptr[n], end = g_rowptr[n + 1];
    float denom = 0.f;
    float ac0 = 0, ac1 = 0, ac2 = 0, ac3 = 0, ac4 = 0, ac5 = 0, ac6 = 0, ac7 = 0;
    float ae0 = 0, ae1 = 0, ae2 = 0, ae3 = 0, ae4 = 0, ae5 = 0, ae6 = 0, ae7 = 0;

    for (int j = beg; j < end; j++) {
        int s = g_esrc[j];
        size_t sbv = (size_t)s * 256;
        const float* eap = g_eacsr + (size_t)j * 32 + (chunk << 3);
        float4 ka = *(const float4*)(kg + sbv + off);
        float4 kb = *(const float4*)(kg + sbv + off + 4);
        float4 aa = *(const float4*)(eap);
        float4 ab = *(const float4*)(eap + 4);
        float part = qa.x * ka.x + qa.y * ka.y + qa.z * ka.z + qa.w * ka.w
                   + qb.x * kb.x + qb.y * kb.y + qb.z * kb.z + qb.w * kb.w
                   + pa.x * aa.x + pa.y * aa.y + pa.z * aa.z + pa.w * aa.w
                   + pb.x * ab.x + pb.y * ab.y + pb.z * ab.z + pb.w * ab.w;
        part += __shfl_xor_sync(0xffffffffu, part, 1);
        part += __shfl_xor_sync(0xffffffffu, part, 2);
        float ex = __expf(part * 0.17677669529663687f);

        float4 va = *(const float4*)(vg + sbv + off);
        float4 vb = *(const float4*)(vg + sbv + off + 4);

        denom += ex;
        ac0 = fmaf(ex, va.x, ac0);  ac1 = fmaf(ex, va.y, ac1);
        ac2 = fmaf(ex, va.z, ac2);  ac3 = fmaf(ex, va.w, ac3);
        ac4 = fmaf(ex, vb.x, ac4);  ac5 = fmaf(ex, vb.y, ac5);
        ac6 = fmaf(ex, vb.z, ac6);  ac7 = fmaf(ex, vb.w, ac7);
        ae0 = fmaf(ex, aa.x, ae0);  ae1 = fmaf(ex, aa.y, ae1);
        ae2 = fmaf(ex, aa.z, ae2);  ae3 = fmaf(ex, aa.w, ae3);
        ae4 = fmaf(ex, ab.x, ae4);  ae5 = fmaf(ex, ab.y, ae5);
        ae6 = fmaf(ex, ab.z, ae6);  ae7 = fmaf(ex, ab.w, ae7);
    }

    float inv = 1.f / (denom + 1e-16f);
    float* st = stage[wid];
    int sbase = h * 33 + chunk * 8;
    st[sbase + 0] = ae0 * inv; st[sbase + 1] = ae1 * inv;
    st[sbase + 2] = ae2 * inv; st[sbase + 3] = ae3 * inv;
    st[sbase + 4] = ae4 * inv; st[sbase + 5] = ae5 * inv;
    st[sbase + 6] = ae6 * inv; st[sbase + 7] = ae7 * inv;
    __syncwarp();

    float4 e0 = make_float4(0.f, 0.f, 0.f, 0.f);
    float4 e1 = make_float4(0.f, 0.f, 0.f, 0.f);
    const float* wb = &W2[h * HS2 + chunk * 8];
#pragma unroll
    for (int d = 0; d < 32; d++) {
        float av = st[h * 33 + d];
        float4 w0 = *(const float4*)(wb + d * 32);
        float4 w1 = *(const float4*)(wb + d * 32 + 4);
        e0.x += av * w0.x; e0.y += av * w0.y; e0.z += av * w0.z; e0.w += av * w0.w;
        e1.x += av * w1.x; e1.y += av * w1.y; e1.z += av * w1.z; e1.w += av * w1.w;
    }

    float v[8];
    v[0] = ac0 * inv + e0.x;  v[1] = ac1 * inv + e0.y;
    v[2] = ac2 * inv + e0.z;  v[3] = ac3 * inv + e0.w;
    v[4] = ac4 * inv + e1.x;  v[5] = ac5 * inv + e1.y;
    v[6] = ac6 * inv + e1.z;  v[7] = ac7 * inv + e1.w;

    // head mean: sum over lanes stride-4 (same col-within-head, different head)
#pragma unroll
    for (int j = 0; j < 8; j++) {
        v[j] += __shfl_xor_sync(0xffffffffu, v[j], 4);
        v[j] += __shfl_xor_sync(0xffffffffu, v[j], 8);
        v[j] += __shfl_xor_sync(0xffffffffu, v[j], 16);
    }
    int c0 = chunk * 8;   // col within 32-dim mean
    float4 s2a = *(const float4*)(skip2 + (size_t)n * 32 + c0);
    float4 s2b = *(const float4*)(skip2 + (size_t)n * 32 + c0 + 4);
    float sv[8] = {s2a.x, s2a.y, s2a.z, s2a.w, s2b.x, s2b.y, s2b.z, s2b.w};
    float d0 = 0.f, d1 = 0.f;
#pragma unroll
    for (int j = 0; j < 8; j++) {
        float z = fmaxf(v[j] * 0.125f + sv[j], 0.f);
        d0 += z * wcs[(c0 + j) * 2 + 0];
        d1 += z * wcs[(c0 + j) * 2 + 1];
    }
    d0 += __shfl_xor_sync(0xffffffffu, d0, 1);
    d0 += __shfl_xor_sync(0xffffffffu, d0, 2);
    d1 += __shfl_xor_sync(0xffffffffu, d1, 1);
    d1 += __shfl_xor_sync(0xffffffffu, d1, 2);
    if (lane == 0) {
        out[(size_t)n * 2 + 0] = d0 + bcs[0];
        out[(size_t)n * 2 + 1] = d1 + bcs[1];
    }
}

// ------------------------- skip2: out[N,32] = h[N,256] @ w[256,32] + b -------------------------
__global__ __launch_bounds__(256) void skip2_kernel(
    const float* __restrict__ hin, const float* __restrict__ w,
    const float* __restrict__ b, float* __restrict__ out, int M)
{
    __shared__ float ws[8192];
    __shared__ float xs[8][256];
    int tid = threadIdx.x;
    for (int i = tid; i < 8192; i += 256) ws[i] = w[i];
    int base = blockIdx.x * 8;
    for (int i = 0; i < 8; i++) {
        int n = base + i;
        xs[i][tid] = (n < M) ? hin[(size_t)n * 256 + tid] : 0.f;
    }
    __syncthreads();
    int r = tid >> 5, c = tid & 31;
    float s = b[c];
#pragma unroll 8
    for (int k = 0; k < 256; k++) s += xs[r][k] * ws[k * 32 + c];
    int n = base + r;
    if (n < M) out[(size_t)n * 32 + c] = s;
}

// ------------------------- launcher -------------------------
extern "C" void kernel_launch(void* const* d_in, const int* in_sizes, int n_in,
                              void* d_out, int out_size)
{
    const float* x      = (const float*)d_in[0];
    const int*   eidx   = (const int*)d_in[1];
    const float* eattr  = (const float*)d_in[2];
    const float* wq1    = (const float*)d_in[3];
    const float* bq1    = (const float*)d_in[4];
    const float* wk1    = (const float*)d_in[5];
    const float* bk1    = (const float*)d_in[6];
    const float* wv1    = (const float*)d_in[7];
    const float* bv1    = (const float*)d_in[8];
    const float* we1    = (const float*)d_in[9];
    const float* wskip1 = (const float*)d_in[10];
    const float* bskip1 = (const float*)d_in[11];
    const float* g1     = (const float*)d_in[12];
    const float* b1     = (const float*)d_in[13];
    const float* wq2    = (const float*)d_in[14];
    const float* bq2    = (const float*)d_in[15];
    const float* wk2    = (const float*)d_in[16];
    const float* bk2    = (const float*)d_in[17];
    const float* wv2    = (const float*)d_in[18];
    const float* bv2    = (const float*)d_in[19];
    const float* we2    = (const float*)d_in[20];
    const float* wskip2 = (const float*)d_in[21];
    const float* bskip2 = (const float*)d_in[22];
    const float* wc     = (const float*)d_in[23];
    const float* bc     = (const float*)d_in[24];

    int n = in_sizes[0] / 128;
    int e = in_sizes[1] / 2;
    const int* src = eidx;
    const int* dst = eidx + e;

    float *pq, *pk, *pv, *pp, *ps1, *ph, *ps2;
    __nv_bfloat16 *pah, *pal, *pbh, *pbl;
    cudaGetSymbolAddress((void**)&pq, g_q);
    cudaGetSymbolAddress((void**)&pk, g_k);
    cudaGetSymbolAddress((void**)&pv, g_v);
    cudaGetSymbolAddress((void**)&pp, g_p);
    cudaGetSymbolAddress((void**)&ps1, g_skip1);
    cudaGetSymbolAddress((void**)&ph, g_h);
    cudaGetSymbolAddress((void**)&ps2, g_skip2);
    cudaGetSymbolAddress((void**)&pah, g_ah);
    cudaGetSymbolAddress((void**)&pal, g_al);
    cudaGetSymbolAddress((void**)&pbh, g_bth);
    cudaGetSymbolAddress((void**)&pbl, g_btl);

    cudaFuncSetAttribute(mma_gemm_kernel,
                         cudaFuncAttributeMaxDynamicSharedMemorySize, GEMM_SMEM);

    int nb256 = (n + 255) / 256;
    int eb256 = (e + 255) / 256;
    int nodeBlocks = (n + 7) / 8;
    int mTiles = (n + 127) / 128;

    // Layer-1 projections (mma_gemm stays at launch index 3 for the ncu window)
    conv_a_kernel<<<(n * 128 + 255) / 256, 256>>>(x, n * 128);
    pack_w_kernel<<<(1024 * 128 + 255) / 256, 256>>>(wq1, wk1, wv1, wskip1, 128, 1024);
    zero_deg_kernel<<<nb256, 256>>>(n);
    {
        dim3 grid(4, mTiles);
        mma_gemm_kernel<<<grid, 256, GEMM_SMEM>>>(pah, pal, pbh, pbl,
                                                  bq1, bk1, bv1, bskip1,
                                                  pq, pk, pv, ps1, 128);
    }
    hist_kernel<<<eb256, 256>>>(dst, e);
    scan_kernel<<<1, 1024>>>(n);
    scatter_kernel<<<eb256, 256>>>(src, dst, e);
    reorder_ea_kernel<<<(e * 8 + 255) / 256, 256>>>(eattr, e);

    compute_p_kernel<<<nodeBlocks, 256>>>(pq, we1, pp, n);
    fused_attn1_kernel<<<nodeBlocks, 256>>>(pq, pk, pv, pp,
                                            we1, ps1, g1, b1, ph, pah, pal, n);

    // Layer 2 (pah/pal already produced by fused_attn1)
    pack_w_kernel<<<(768 * 256 + 255) / 256, 256>>>(wq2, wk2, wv2, wv2, 256, 768);
    {
        dim3 grid(3, mTiles);
        mma_gemm_kernel<<<grid, 256, GEMM_SMEM>>>(pah, pal, pbh, pbl,
                                                  bq2, bk2, bv2, bv2,
                                                  pq, pk, pv, pv, 256);
    }
    skip2_kernel<<<nodeBlocks, 256>>>(ph, wskip2, bskip2, ps2, n);
    compute_p_kernel<<<nodeBlocks, 256>>>(pq, we2, pp, n);
    fused_attn2_kernel<<<nodeBlocks, 256>>>(pq, pk, pv, pp,
                                            we2, ps2, wc, bc, (float*)d_out, n);
}

// round 15
// speedup vs baseline: 1.3267x; 1.1034x over previous
#include <cuda_runtime.h>
#include <cuda_bf16.h>
#include <math.h>
#include <stdint.h>

#define NMAX 50000
#define NPAD 50048   // 391 * 128
#define EMAX 400000
#define HS2 1028     // per-head stride in W2 smem (conflict-free: 1028 % 32 == 4)

// ------------------------- scratch (static device memory) -------------------------
__device__ float g_q[(size_t)NPAD * 256];
__device__ float g_k[(size_t)NPAD * 256];
__device__ float g_v[(size_t)NPAD * 256];
__device__ float g_p[(size_t)NPAD * 256];
__device__ float g_skip1[(size_t)NPAD * 256];
__device__ float g_h[(size_t)NPAD * 256];
__device__ float g_skip2[(size_t)NPAD * 32];
__device__ float g_eacsr[(size_t)EMAX * 32];
__device__ __nv_bfloat16 g_ah[(size_t)NPAD * 256];
__device__ __nv_bfloat16 g_al[(size_t)NPAD * 256];
__device__ __nv_bfloat16 g_bth[1024 * 256];
__device__ __nv_bfloat16 g_btl[1024 * 256];
__device__ int g_deg[NMAX];
__device__ int g_rowptr[NMAX + 1];
__device__ int g_cnt[NMAX];
__device__ int g_eid[EMAX];
__device__ int g_esrc[EMAX];

// ------------------------- PTX helpers -------------------------
__device__ __forceinline__ uint32_t smem_u32(const void* p) {
    uint32_t a;
    asm("{ .reg .u64 t; cvta.to.shared.u64 t, %1; cvt.u32.u64 %0, t; }" : "=r"(a) : "l"(p));
    return a;
}
__device__ __forceinline__ void cp16(uint32_t saddr, const void* gaddr) {
    asm volatile("cp.async.cg.shared.global [%0], [%1], 16;" :: "r"(saddr), "l"(gaddr) : "memory");
}
#define CP_COMMIT() asm volatile("cp.async.commit_group;" ::: "memory")
#define CP_WAIT(N)  asm volatile("cp.async.wait_group %0;" :: "n"(N) : "memory")

__device__ __forceinline__ void ldm_x4(uint32_t* r, uint32_t addr) {
    asm volatile("ldmatrix.sync.aligned.m8n8.x4.shared.b16 {%0,%1,%2,%3}, [%4];"
        : "=r"(r[0]), "=r"(r[1]), "=r"(r[2]), "=r"(r[3]) : "r"(addr));
}
__device__ __forceinline__ void mma_bf16(float* c, const uint32_t* a, const uint32_t* b) {
    asm volatile("mma.sync.aligned.m16n8k16.row.col.f32.bf16.bf16.f32 "
        "{%0,%1,%2,%3}, {%4,%5,%6,%7}, {%8,%9}, {%0,%1,%2,%3};"
        : "+f"(c[0]), "+f"(c[1]), "+f"(c[2]), "+f"(c[3])
        : "r"(a[0]), "r"(a[1]), "r"(a[2]), "r"(a[3]), "r"(b[0]), "r"(b[1]));
}

// ------------------------- CSR build -------------------------
__global__ void zero_deg_kernel(int n) {
    int i = blockIdx.x * blockDim.x + threadIdx.x;
    if (i < n) g_deg[i] = 0;
}
__global__ void hist_kernel(const int* __restrict__ dst, int e) {
    int i = blockIdx.x * blockDim.x + threadIdx.x;
    if (i < e) atomicAdd(&g_deg[dst[i]], 1);
}
__global__ void scan_kernel(int n) {
    __shared__ int sums[1024];
    int tid = threadIdx.x;
    int per = (n + 1023) >> 10;
    int beg = tid * per;
    int end = min(beg + per, n);
    int s = 0;
    for (int i = beg; i < end; i++) s += g_deg[i];
    sums[tid] = s;
    __syncthreads();
    for (int o = 1; o < 1024; o <<= 1) {
        int v = (tid >= o) ? sums[tid - o] : 0;
        __syncthreads();
        sums[tid] += v;
        __syncthreads();
    }
    int run = (tid == 0) ? 0 : sums[tid - 1];
    for (int i = beg; i < end; i++) {
        g_rowptr[i] = run;
        g_cnt[i] = run;
        run += g_deg[i];
    }
    if (tid == 1023) g_rowptr[n] = sums[1023];
}
__global__ void scatter_kernel(const int* __restrict__ src, const int* __restrict__ dst, int e) {
    int i = blockIdx.x * blockDim.x + threadIdx.x;
    if (i < e) {
        int pos = atomicAdd(&g_cnt[dst[i]], 1);
        g_eid[pos] = i;
        g_esrc[pos] = src[i];
    }
}
// reorder edge_attr into CSR order: 8 lanes per slot, random 128B reads, sequential writes
__global__ void reorder_ea_kernel(const float* __restrict__ ea, int e) {
    int gtid = blockIdx.x * blockDim.x + threadIdx.x;
    int j = gtid >> 3, part = gtid & 7;
    if (j < e) {
        int src_e = g_eid[j];
        *(float4*)(g_eacsr + (size_t)j * 32 + part * 4) =
            *(const float4*)(ea + (size_t)src_e * 32 + part * 4);
    }
}

// ------------------------- fp32 -> bf16 hi/lo split (layer-1 input only) ----------
__global__ void conv_a_kernel(const float* __restrict__ a, int total) {
    int i = blockIdx.x * blockDim.x + threadIdx.x;
    if (i < total) {
        float v = a[i];
        __nv_bfloat16 h = __float2bfloat16(v);
        g_ah[i] = h;
        g_al[i] = __float2bfloat16(v - __bfloat162float(h));
    }
}

// pack W segments [K,256] row-major into bt[NC,K] K-major bf16 hi/lo
__global__ void pack_w_kernel(const float* __restrict__ w0, const float* __restrict__ w1,
                              const float* __restrict__ w2, const float* __restrict__ w3,
                              int K, int NC) {
    int idx = blockIdx.x * blockDim.x + threadIdx.x;
    if (idx >= NC * K) return;
    int nc = idx / K, k = idx - nc * K;
    int seg = nc >> 8, c = nc & 255;
    const float* w = (seg == 0) ? w0 : (seg == 1) ? w1 : (seg == 2) ? w2 : w3;
    float v = w[(size_t)k * 256 + c];
    __nv_bfloat16 h = __float2bfloat16(v);
    g_bth[idx] = h;
    g_btl[idx] = __float2bfloat16(v - __bfloat162float(h));
}

// ------------------------- mma.sync bf16-split GEMM, 128x256 CTA tile -------------------------
#define ATILE 10240
#define BTILE 20480
#define STAGEB (2 * ATILE + 2 * BTILE)
#define GEMM_SMEM (2 * STAGEB)

__global__ __launch_bounds__(256, 1) void mma_gemm_kernel(
    const __nv_bfloat16* __restrict__ ah, const __nv_bfloat16* __restrict__ al,
    const __nv_bfloat16* __restrict__ bth, const __nv_bfloat16* __restrict__ btl,
    const float* __restrict__ b0, const float* __restrict__ b1,
    const float* __restrict__ b2, const float* __restrict__ b3,
    float* __restrict__ o0, float* __restrict__ o1,
    float* __restrict__ o2, float* __restrict__ o3,
    int K)
{
    extern __shared__ __align__(128) char smem[];
    uint32_t sb = smem_u32(smem);
    int tid = threadIdx.x;
    int wid = tid >> 5, lane = tid & 31;
    int seg = blockIdx.x;
    int gRow = blockIdx.y * 128;

    const __nv_bfloat16* aH = ah + (size_t)gRow * K;
    const __nv_bfloat16* aL = al + (size_t)gRow * K;
    const __nv_bfloat16* bH = bth + (size_t)seg * 256 * K;
    const __nv_bfloat16* bL = btl + (size_t)seg * 256 * K;

    int chunks = K >> 5;

    auto load_stage = [&](int c, int s) {
        uint32_t base = sb + s * STAGEB;
        int kc = c << 5;
#pragma unroll
        for (int i = 0; i < 2; i++) {
            int cid = tid + i * 256;
            int r = cid >> 2, ch = cid & 3;
            uint32_t sa = base + r * 80 + ch * 16;
            size_t go = (size_t)r * K + kc + ch * 8;
            cp16(sa, aH + go);
            cp16(sa + ATILE, aL + go);
        }
#pragma unroll
        for (int i = 0; i < 4; i++) {
            int cid = tid + i * 256;
            int r = cid >> 2, ch = cid & 3;
            uint32_t sa = base + 2 * ATILE + r * 80 + ch * 16;
            size_t go = (size_t)r * K + kc + ch * 8;
            cp16(sa, bH + go);
            cp16(sa + BTILE, bL + go);
        }
        CP_COMMIT();
    };

    float acc[4][8][4];
#pragma unroll
    for (int a = 0; a < 4; a++)
#pragma unroll
        for (int b = 0; b < 8; b++)
#pragma unroll
            for (int c = 0; c < 4; c++) acc[a][b][c] = 0.f;

    int warp_m = wid >> 2, warp_n = wid & 3;
    int mrow0 = warp_m * 64, ncol0 = warp_n * 64;
    int lrow = lane & 15, lsel = lane >> 4;
    int bnrow = (lane >> 4) * 8 + (lane & 7);
    int bgk = ((lane >> 3) & 1) * 16;

    load_stage(0, 0);

    for (int c = 0; c < chunks; c++) {
        if (c + 1 < chunks) { load_stage(c + 1, (c + 1) & 1); CP_WAIT(1); }
        else CP_WAIT(0);
        __syncthreads();

        uint32_t base = sb + (c & 1) * STAGEB;
#pragma unroll
        for (int kh = 0; kh < 2; kh++) {
            uint32_t a_h[4][4], a_l[4][4];
#pragma unroll
            for (int mt = 0; mt < 4; mt++) {
                uint32_t ra = base + (mrow0 + mt * 16 + lrow) * 80 + kh * 32 + lsel * 16;
                ldm_x4(a_h[mt], ra);
                ldm_x4(a_l[mt], ra + ATILE);
            }
#pragma unroll
            for (int ntp = 0; ntp < 4; ntp++) {
                uint32_t b_h[4], b_l[4];
                uint32_t rb = base + 2 * ATILE + (ncol0 + ntp * 16 + bnrow) * 80 + kh * 32 + bgk;
                ldm_x4(b_h, rb);
                ldm_x4(b_l, rb + BTILE);
#pragma unroll
                for (int mt = 0; mt < 4; mt++) {
                    mma_bf16(acc[mt][2 * ntp],     a_h[mt], b_h);
                    mma_bf16(acc[mt][2 * ntp],     a_h[mt], b_l);
                    mma_bf16(acc[mt][2 * ntp],     a_l[mt], b_h);
                    mma_bf16(acc[mt][2 * ntp + 1], a_h[mt], b_h + 2);
                    mma_bf16(acc[mt][2 * ntp + 1], a_h[mt], b_l + 2);
                    mma_bf16(acc[mt][2 * ntp + 1], a_l[mt], b_h + 2);
                }
            }
        }
        __syncthreads();
    }

    const float* bias = (seg == 0) ? b0 : (seg == 1) ? b1 : (seg == 2) ? b2 : b3;
    float* out = (seg == 0) ? o0 : (seg == 1) ? o1 : (seg == 2) ? o2 : o3;
    int colBase = ncol0 + (lane & 3) * 2;
    int row0 = gRow + mrow0 + (lane >> 2);
#pragma unroll
    for (int mt = 0; mt < 4; mt++) {
        int row = row0 + mt * 16;
#pragma unroll
        for (int nt = 0; nt < 8; nt++) {
            int col = colBase + nt * 8;
            float bv0 = bias[col], bv1 = bias[col + 1];
            float2 v0 = make_float2(acc[mt][nt][0] + bv0, acc[mt][nt][1] + bv1);
            float2 v1 = make_float2(acc[mt][nt][2] + bv0, acc[mt][nt][3] + bv1);
            *(float2*)(out + (size_t)row * 256 + col) = v0;
            *(float2*)(out + (size_t)(row + 8) * 256 + col) = v1;
        }
    }
}

// ------------------------- p[n][h*32+d] = sum_c q[n][h*32+c] * we[d][h*32+c] -------------------------
__global__ __launch_bounds__(256) void compute_p_kernel(
    const float* __restrict__ q, const float* __restrict__ we,
    float* __restrict__ p, int M)
{
    __shared__ float wet[256 * 33];
    __shared__ float qs[8][256];
    int tid = threadIdx.x;
    for (int i = tid; i < 8192; i += 256) {
        int d = i >> 8, col = i & 255;
        wet[col * 33 + d] = we[i];
    }
    int base = blockIdx.x * 8;
    for (int i = 0; i < 8; i++) {
        int n = base + i;
        qs[i][tid] = (n < M) ? q[(size_t)n * 256 + tid] : 0.f;
    }
    __syncthreads();
    int h = tid >> 5, d = tid & 31;
    for (int i = 0; i < 8; i++) {
        int n = base + i;
        if (n >= M) break;
        float s = 0.f;
#pragma unroll
        for (int c = 0; c < 32; c++)
            s += qs[i][h * 32 + c] * wet[(h * 32 + c) * 33 + d];
        p[(size_t)n * 256 + h * 32 + d] = s;
    }
}

// ============== fused edge attention + epilogue, LAYER 1 ==============
__global__ __launch_bounds__(256) void fused_attn1_kernel(
    const float* __restrict__ qg, const float* __restrict__ kg,
    const float* __restrict__ vg, const float* __restrict__ pg,
    const float* __restrict__ we, const float* __restrict__ skip,
    const float* __restrict__ g, const float* __restrict__ b,
    float* __restrict__ hout, __nv_bfloat16* __restrict__ ahout,
    __nv_bfloat16* __restrict__ alout, int M)
{
    __shared__ __align__(16) float W2[8224];
    __shared__ float stage[8][264];
    __shared__ float gsh[256], bsh[256];
    int tid = threadIdx.x;
    for (int i = tid; i < 8192; i += 256) {
        int d = i >> 8, col = i & 255;
        W2[(col >> 5) * HS2 + d * 32 + (col & 31)] = we[i];
    }
    gsh[tid] = g[tid];
    bsh[tid] = b[tid];
    __syncthreads();

    int wid = tid >> 5, lane = tid & 31;
    int n = blockIdx.x * 8 + wid;
    if (n >= M) return;
    int h = lane >> 2, chunk = lane & 3, off = lane << 3;
    size_t nb = (size_t)n * 256;

    float4 qa = *(const float4*)(qg + nb + off);
    float4 qb = *(const float4*)(qg + nb + off + 4);
    float4 pa = *(const float4*)(pg + nb + off);
    float4 pb = *(const float4*)(pg + nb + off + 4);

    int beg = g_rowptr[n], end = g_rowptr[n + 1];
    float denom = 0.f;
    float ac0 = 0, ac1 = 0, ac2 = 0, ac3 = 0, ac4 = 0, ac5 = 0, ac6 = 0, ac7 = 0;
    float ae0 = 0, ae1 = 0, ae2 = 0, ae3 = 0, ae4 = 0, ae5 = 0, ae6 = 0, ae7 = 0;

    for (int j = beg; j < end; j++) {
        int s = g_esrc[j];
        size_t sbv = (size_t)s * 256;
        const float* eap = g_eacsr + (size_t)j * 32 + (chunk << 3);
        float4 ka = *(const float4*)(kg + sbv + off);
        float4 kb = *(const float4*)(kg + sbv + off + 4);
        float4 aa = *(const float4*)(eap);
        float4 ab = *(const float4*)(eap + 4);
        float part = qa.x * ka.x + qa.y * ka.y + qa.z * ka.z + qa.w * ka.w
                   + qb.x * kb.x + qb.y * kb.y + qb.z * kb.z + qb.w * kb.w
                   + pa.x * aa.x + pa.y * aa.y + pa.z * aa.z + pa.w * aa.w
                   + pb.x * ab.x + pb.y * ab.y + pb.z * ab.z + pb.w * ab.w;
        part += __shfl_xor_sync(0xffffffffu, part, 1);
        part += __shfl_xor_sync(0xffffffffu, part, 2);
        float ex = __expf(part * 0.17677669529663687f);

        float4 va = *(const float4*)(vg + sbv + off);
        float4 vb = *(const float4*)(vg + sbv + off + 4);

        denom += ex;
        ac0 = fmaf(ex, va.x, ac0);  ac1 = fmaf(ex, va.y, ac1);
        ac2 = fmaf(ex, va.z, ac2);  ac3 = fmaf(ex, va.w, ac3);
        ac4 = fmaf(ex, vb.x, ac4);  ac5 = fmaf(ex, vb.y, ac5);
        ac6 = fmaf(ex, vb.z, ac6);  ac7 = fmaf(ex, vb.w, ac7);
        ae0 = fmaf(ex, aa.x, ae0);  ae1 = fmaf(ex, aa.y, ae1);
        ae2 = fmaf(ex, aa.z, ae2);  ae3 = fmaf(ex, aa.w, ae3);
        ae4 = fmaf(ex, ab.x, ae4);  ae5 = fmaf(ex, ab.y, ae5);
        ae6 = fmaf(ex, ab.z, ae6);  ae7 = fmaf(ex, ab.w, ae7);
    }

    float inv = 1.f / (denom + 1e-16f);
    float* st = stage[wid];
    int sbase = h * 33 + chunk * 8;
    st[sbase + 0] = ae0 * inv; st[sbase + 1] = ae1 * inv;
    st[sbase + 2] = ae2 * inv; st[sbase + 3] = ae3 * inv;
    st[sbase + 4] = ae4 * inv; st[sbase + 5] = ae5 * inv;
    st[sbase + 6] = ae6 * inv; st[sbase + 7] = ae7 * inv;
    __syncwarp();

    float4 e0 = make_float4(0.f, 0.f, 0.f, 0.f);
    float4 e1 = make_float4(0.f, 0.f, 0.f, 0.f);
    const float* wb = &W2[h * HS2 + chunk * 8];
#pragma unroll
    for (int d = 0; d < 32; d++) {
        float av = st[h * 33 + d];
        float4 w0 = *(const float4*)(wb + d * 32);
        float4 w1 = *(const float4*)(wb + d * 32 + 4);
        e0.x += av * w0.x; e0.y += av * w0.y; e0.z += av * w0.z; e0.w += av * w0.w;
        e1.x += av * w1.x; e1.y += av * w1.y; e1.z += av * w1.z; e1.w += av * w1.w;
    }

    float4 sk0 = *(const float4*)(skip + nb + off);
    float4 sk1 = *(const float4*)(skip + nb + off + 4);
    float v0 = fmaxf(ac0 * inv + e0.x + sk0.x, 0.f);
    float v1 = fmaxf(ac1 * inv + e0.y + sk0.y, 0.f);
    float v2 = fmaxf(ac2 * inv + e0.z + sk0.z, 0.f);
    float v3 = fmaxf(ac3 * inv + e0.w + sk0.w, 0.f);
    float v4 = fmaxf(ac4 * inv + e1.x + sk1.x, 0.f);
    float v5 = fmaxf(ac5 * inv + e1.y + sk1.y, 0.f);
    float v6 = fmaxf(ac6 * inv + e1.z + sk1.z, 0.f);
    float v7 = fmaxf(ac7 * inv + e1.w + sk1.w, 0.f);

    float s1 = v0 + v1 + v2 + v3 + v4 + v5 + v6 + v7;
    float s2 = v0 * v0 + v1 * v1 + v2 * v2 + v3 * v3 + v4 * v4 + v5 * v5 + v6 * v6 + v7 * v7;
#pragma unroll
    for (int o = 16; o > 0; o >>= 1) {
        s1 += __shfl_xor_sync(0xffffffffu, s1, o);
        s2 += __shfl_xor_sync(0xffffffffu, s2, o);
    }
    float mu = s1 * (1.f / 256.f);
    float var = s2 * (1.f / 256.f) - mu * mu;
    float rinv = rsqrtf(var + 1e-5f);

    float o0 = (v0 - mu) * rinv * gsh[off + 0] + bsh[off + 0];
    float o1 = (v1 - mu) * rinv * gsh[off + 1] + bsh[off + 1];
    float o2 = (v2 - mu) * rinv * gsh[off + 2] + bsh[off + 2];
    float o3 = (v3 - mu) * rinv * gsh[off + 3] + bsh[off + 3];
    float o4 = (v4 - mu) * rinv * gsh[off + 4] + bsh[off + 4];
    float o5 = (v5 - mu) * rinv * gsh[off + 5] + bsh[off + 5];
    float o6 = (v6 - mu) * rinv * gsh[off + 6] + bsh[off + 6];
    float o7 = (v7 - mu) * rinv * gsh[off + 7] + bsh[off + 7];

    *(float4*)(hout + nb + off)     = make_float4(o0, o1, o2, o3);
    *(float4*)(hout + nb + off + 4) = make_float4(o4, o5, o6, o7);

    float ov[8] = {o0, o1, o2, o3, o4, o5, o6, o7};
    __nv_bfloat16 hi[8];
    __nv_bfloat16 lo[8];
#pragma unroll
    for (int j = 0; j < 8; j++) {
        hi[j] = __float2bfloat16(ov[j]);
        lo[j] = __float2bfloat16(ov[j] - __bfloat162float(hi[j]));
    }
    *(uint4*)(ahout + nb + off) = *(uint4*)hi;
    *(uint4*)(alout + nb + off) = *(uint4*)lo;
}

// ============== fused edge attention + epilogue, LAYER 2 ==============
__global__ __launch_bounds__(256) void fused_attn2_kernel(
    const float* __restrict__ qg, const float* __restrict__ kg,
    const float* __restrict__ vg, const float* __restrict__ pg,
    const float* __restrict__ we, const float* __restrict__ skip2,
    const float* __restrict__ wc, const float* __restrict__ bc,
    float* __restrict__ out, int M)
{
    __shared__ __align__(16) float W2[8224];
    __shared__ float stage[8][264];
    __shared__ float wcs[64];
    __shared__ float bcs[2];
    int tid = threadIdx.x;
    for (int i = tid; i < 8192; i += 256) {
        int d = i >> 8, col = i & 255;
        W2[(col >> 5) * HS2 + d * 32 + (col & 31)] = we[i];
    }
    if (tid < 64) wcs[tid] = wc[tid];
    if (tid < 2) bcs[tid] = bc[tid];
    __syncthreads();

    int wid = tid >> 5, lane = tid & 31;
    int n = blockIdx.x * 8 + wid;
    if (n >= M) return;
    int h = lane >> 2, chunk = lane & 3, off = lane << 3;
    size_t nb = (size_t)n * 256;

    float4 qa = *(const float4*)(qg + nb + off);
    float4 qb = *(const float4*)(qg + nb + off + 4);
    float4 pa = *(const float4*)(pg + nb + off);
    float4 pb = *(const float4*)(pg + nb + off + 4);

    int beg = g_rowptr[n], end = g_rowptr[n + 1];
    float denom = 0.f;
    float ac0 = 0, ac1 = 0, ac2 = 0, ac3 = 0, ac4 = 0, ac5 = 0, ac6 = 0, ac7 = 0;
    float ae0 = 0, ae1 = 0, ae2 = 0, ae3 = 0, ae4 = 0, ae5 = 0, ae6 = 0, ae7 = 0;

    for (int j = beg; j < end; j++) {
        int s = g_esrc[j];
        size_t sbv = (size_t)s * 256;
        const float* eap = g_eacsr + (size_t)j * 32 + (chunk << 3);
        float4 ka = *(const float4*)(kg + sbv + off);
        float4 kb = *(const float4*)(kg + sbv + off + 4);
        float4 aa = *(const float4*)(eap);
        float4 ab = *(const float4*)(eap + 4);
        float part = qa.x * ka.x + qa.y * ka.y + qa.z * ka.z + qa.w * ka.w
                   + qb.x * kb.x + qb.y * kb.y + qb.z * kb.z + qb.w * kb.w
                   + pa.x * aa.x + pa.y * aa.y + pa.z * aa.z + pa.w * aa.w
                   + pb.x * ab.x + pb.y * ab.y + pb.z * ab.z + pb.w * ab.w;
        part += __shfl_xor_sync(0xffffffffu, part, 1);
        part += __shfl_xor_sync(0xffffffffu, part, 2);
        float ex = __expf(part * 0.17677669529663687f);

        float4 va = *(const float4*)(vg + sbv + off);
        float4 vb = *(const float4*)(vg + sbv + off + 4);

        denom += ex;
        ac0 = fmaf(ex, va.x, ac0);  ac1 = fmaf(ex, va.y, ac1);
        ac2 = fmaf(ex, va.z, ac2);  ac3 = fmaf(ex, va.w, ac3);
        ac4 = fmaf(ex, vb.x, ac4);  ac5 = fmaf(ex, vb.y, ac5);
        ac6 = fmaf(ex, vb.z, ac6);  ac7 = fmaf(ex, vb.w, ac7);
        ae0 = fmaf(ex, aa.x, ae0);  ae1 = fmaf(ex, aa.y, ae1);
        ae2 = fmaf(ex, aa.z, ae2);  ae3 = fmaf(ex, aa.w, ae3);
        ae4 = fmaf(ex, ab.x, ae4);  ae5 = fmaf(ex, ab.y, ae5);
        ae6 = fmaf(ex, ab.z, ae6);  ae7 = fmaf(ex, ab.w, ae7);
    }

    float inv = 1.f / (denom + 1e-16f);
    float* st = stage[wid];
    int sbase = h * 33 + chunk * 8;
    st[sbase + 0] = ae0 * inv; st[sbase + 1] = ae1 * inv;
    st[sbase + 2] = ae2 * inv; st[sbase + 3] = ae3 * inv;
    st[sbase + 4] = ae4 * inv; st[sbase + 5] = ae5 * inv;
    st[sbase + 6] = ae6 * inv; st[sbase + 7] = ae7 * inv;
    __syncwarp();

    float4 e0 = make_float4(0.f, 0.f, 0.f, 0.f);
    float4 e1 = make_float4(0.f, 0.f, 0.f, 0.f);
    const float* wb = &W2[h * HS2 + chunk * 8];
#pragma unroll
    for (int d = 0; d < 32; d++) {
        float av = st[h * 33 + d];
        float4 w0 = *(const float4*)(wb + d * 32);
        float4 w1 = *(const float4*)(wb + d * 32 + 4);
        e0.x += av * w0.x; e0.y += av * w0.y; e0.z += av * w0.z; e0.w += av * w0.w;
        e1.x += av * w1.x; e1.y += av * w1.y; e1.z += av * w1.z; e1.w += av * w1.w;
    }

    float v[8];
    v[0] = ac0 * inv + e0.x;  v[1] = ac1 * inv + e0.y;
    v[2] = ac2 * inv + e0.z;  v[3] = ac3 * inv + e0.w;
    v[4] = ac4 * inv + e1.x;  v[5] = ac5 * inv + e1.y;
    v[6] = ac6 * inv + e1.z;  v[7] = ac7 * inv + e1.w;

#pragma unroll
    for (int j = 0; j < 8; j++) {
        v[j] += __shfl_xor_sync(0xffffffffu, v[j], 4);
        v[j] += __shfl_xor_sync(0xffffffffu, v[j], 8);
        v[j] += __shfl_xor_sync(0xffffffffu, v[j], 16);
    }
    int c0 = chunk * 8;
    float4 s2a = *(const float4*)(skip2 + (size_t)n * 32 + c0);
    float4 s2b = *(const float4*)(skip2 + (size_t)n * 32 + c0 + 4);
    float sv[8] = {s2a.x, s2a.y, s2a.z, s2a.w, s2b.x, s2b.y, s2b.z, s2b.w};
    float d0 = 0.f, d1 = 0.f;
#pragma unroll
    for (int j = 0; j < 8; j++) {
        float z = fmaxf(v[j] * 0.125f + sv[j], 0.f);
        d0 += z * wcs[(c0 + j) * 2 + 0];
        d1 += z * wcs[(c0 + j) * 2 + 1];
    }
    d0 += __shfl_xor_sync(0xffffffffu, d0, 1);
    d0 += __shfl_xor_sync(0xffffffffu, d0, 2);
    d1 += __shfl_xor_sync(0xffffffffu, d1, 1);
    d1 += __shfl_xor_sync(0xffffffffu, d1, 2);
    if (lane == 0) {
        out[(size_t)n * 2 + 0] = d0 + bcs[0];
        out[(size_t)n * 2 + 1] = d1 + bcs[1];
    }
}

// ------------------------- skip2: out[N,32] = h[N,256] @ w[256,32] + b -------------------------
__global__ __launch_bounds__(256) void skip2_kernel(
    const float* __restrict__ hin, const float* __restrict__ w,
    const float* __restrict__ b, float* __restrict__ out, int M)
{
    __shared__ float ws[8192];
    __shared__ float xs[8][256];
    int tid = threadIdx.x;
    for (int i = tid; i < 8192; i += 256) ws[i] = w[i];
    int base = blockIdx.x * 8;
    for (int i = 0; i < 8; i++) {
        int n = base + i;
        xs[i][tid] = (n < M) ? hin[(size_t)n * 256 + tid] : 0.f;
    }
    __syncthreads();
    int r = tid >> 5, c = tid & 31;
    float s = b[c];
#pragma unroll 8
    for (int k = 0; k < 256; k++) s += xs[r][k] * ws[k * 32 + c];
    int n = base + r;
    if (n < M) out[(size_t)n * 32 + c] = s;
}

// ------------------------- launcher -------------------------
extern "C" void kernel_launch(void* const* d_in, const int* in_sizes, int n_in,
                              void* d_out, int out_size)
{
    const float* x      = (const float*)d_in[0];
    const int*   eidx   = (const int*)d_in[1];
    const float* eattr  = (const float*)d_in[2];
    const float* wq1    = (const float*)d_in[3];
    const float* bq1    = (const float*)d_in[4];
    const float* wk1    = (const float*)d_in[5];
    const float* bk1    = (const float*)d_in[6];
    const float* wv1    = (const float*)d_in[7];
    const float* bv1    = (const float*)d_in[8];
    const float* we1    = (const float*)d_in[9];
    const float* wskip1 = (const float*)d_in[10];
    const float* bskip1 = (const float*)d_in[11];
    const float* g1     = (const float*)d_in[12];
    const float* b1     = (const float*)d_in[13];
    const float* wq2    = (const float*)d_in[14];
    const float* bq2    = (const float*)d_in[15];
    const float* wk2    = (const float*)d_in[16];
    const float* bk2    = (const float*)d_in[17];
    const float* wv2    = (const float*)d_in[18];
    const float* bv2    = (const float*)d_in[19];
    const float* we2    = (const float*)d_in[20];
    const float* wskip2 = (const float*)d_in[21];
    const float* bskip2 = (const float*)d_in[22];
    const float* wc     = (const float*)d_in[23];
    const float* bc     = (const float*)d_in[24];

    int n = in_sizes[0] / 128;
    int e = in_sizes[1] / 2;
    const int* src = eidx;
    const int* dst = eidx + e;

    float *pq, *pk, *pv, *pp, *ps1, *ph, *ps2;
    __nv_bfloat16 *pah, *pal, *pbh, *pbl;
    cudaGetSymbolAddress((void**)&pq, g_q);
    cudaGetSymbolAddress((void**)&pk, g_k);
    cudaGetSymbolAddress((void**)&pv, g_v);
    cudaGetSymbolAddress((void**)&pp, g_p);
    cudaGetSymbolAddress((void**)&ps1, g_skip1);
    cudaGetSymbolAddress((void**)&ph, g_h);
    cudaGetSymbolAddress((void**)&ps2, g_skip2);
    cudaGetSymbolAddress((void**)&pah, g_ah);
    cudaGetSymbolAddress((void**)&pal, g_al);
    cudaGetSymbolAddress((void**)&pbh, g_bth);
    cudaGetSymbolAddress((void**)&pbl, g_btl);

    cudaFuncSetAttribute(mma_gemm_kernel,
                         cudaFuncAttributeMaxDynamicSharedMemorySize, GEMM_SMEM);

    // side stream + fork/join events (created once; capture-safe fork/join pattern)
    static cudaStream_t s2 = nullptr;
    static cudaEvent_t evFork = nullptr, evCSR = nullptr, evH = nullptr, evSkip2 = nullptr;
    if (!s2) {
        cudaStreamCreateWithFlags(&s2, cudaStreamNonBlocking);
        cudaEventCreateWithFlags(&evFork, cudaEventDisableTiming);
        cudaEventCreateWithFlags(&evCSR, cudaEventDisableTiming);
        cudaEventCreateWithFlags(&evH, cudaEventDisableTiming);
        cudaEventCreateWithFlags(&evSkip2, cudaEventDisableTiming);
    }

    int nb256 = (n + 255) / 256;
    int eb256 = (e + 255) / 256;
    int nodeBlocks = (n + 7) / 8;
    int mTiles = (n + 127) / 128;

    // ---- fork: CSR build + ea reorder + pack_w2 on side stream, under GEMM-L1 ----
    cudaEventRecord(evFork, 0);
    cudaStreamWaitEvent(s2, evFork, 0);
    zero_deg_kernel<<<nb256, 256, 0, s2>>>(n);
    hist_kernel<<<eb256, 256, 0, s2>>>(dst, e);
    scan_kernel<<<1, 1024, 0, s2>>>(n);
    scatter_kernel<<<eb256, 256, 0, s2>>>(src, dst, e);
    reorder_ea_kernel<<<(e * 8 + 255) / 256, 256, 0, s2>>>(eattr, e);
    pack_w_kernel<<<(768 * 256 + 255) / 256, 256, 0, s2>>>(wq2, wk2, wv2, wv2, 256, 768);
    cudaEventRecord(evCSR, s2);

    // ---- main stream: layer-1 projections ----
    conv_a_kernel<<<(n * 128 + 255) / 256, 256>>>(x, n * 128);
    pack_w_kernel<<<(1024 * 128 + 255) / 256, 256>>>(wq1, wk1, wv1, wskip1, 128, 1024);
    {
        dim3 grid(4, mTiles);
        mma_gemm_kernel<<<grid, 256, GEMM_SMEM>>>(pah, pal, pbh, pbl,
                                                  bq1, bk1, bv1, bskip1,
                                                  pq, pk, pv, ps1, 128);
    }
    compute_p_kernel<<<nodeBlocks, 256>>>(pq, we1, pp, n);

    // join: fused1 needs CSR + reordered ea (+ GEMM outputs, already ordered)
    cudaStreamWaitEvent(0, evCSR, 0);
    fused_attn1_kernel<<<nodeBlocks, 256>>>(pq, pk, pv, pp,
                                            we1, ps1, g1, b1, ph, pah, pal, n);

    // ---- fork: skip2 (depends only on ph) under GEMM-L2 ----
    cudaEventRecord(evH, 0);
    cudaStreamWaitEvent(s2, evH, 0);
    skip2_kernel<<<nodeBlocks, 256, 0, s2>>>(ph, wskip2, bskip2, ps2, n);
    cudaEventRecord(evSkip2, s2);

    // ---- main stream: layer 2 (pbh/pbl packed on side stream before evCSR) ----
    {
        dim3 grid(3, mTiles);
        mma_gemm_kernel<<<grid, 256, GEMM_SMEM>>>(pah, pal, pbh, pbl,
                                                  bq2, bk2, bv2, bv2,
                                                  pq, pk, pv, pv, 256);
    }
    compute_p_kernel<<<nodeBlocks, 256>>>(pq, we2, pp, n);

    // join: fused2 needs skip2
    cudaStreamWaitEvent(0, evSkip2, 0);
    fused_attn2_kernel<<<nodeBlocks, 256>>>(pq, pk, pv, pp,
                                            we2, ps2, wc, bc, (float*)d_out, n);
}